// round 4
// baseline (speedup 1.0000x reference)
#include <cuda_runtime.h>
#include <math.h>

#define B_    64
#define L_    197
#define D_    192
#define H_    3
#define DH_   64
#define MM_   128
#define TM_   256           // 2M
#define NT_   (B_*L_)       // 12608
#define FF_   768
#define NCLS_ 1000
#define NP_   (B_*196)      // 12544

// ---------------- scratch (static device globals; no allocation) ----------------
__device__ float g_xc[NT_*D_];
__device__ float g_q [NT_*D_];
__device__ float g_k [NT_*D_];
__device__ float g_v [NT_*D_];
__device__ float g_Qp[NT_*H_*TM_];
__device__ float g_Kp[NT_*H_*TM_];
__device__ float g_KV[B_*H_*TM_*DH_];
__device__ float g_Ks[B_*H_*TM_];
__device__ float g_at[NT_*D_];
__device__ float g_tp[NT_*D_];
__device__ float g_h1[NT_*FF_];
__device__ float g_pl[B_*D_];
__device__ float g_im[NP_*768];

// ---------------- GEMM: C[N,Mo] = A[N,K] @ W[Mo,K]^T (+bias, +add, relu) --------
// 64x64 tile, BK=16, 256 threads, 4x4 register blocking. N must be multiple of 64,
// K multiple of 16. Mo arbitrary (col guards).
__global__ void sgemm_kernel(const float* __restrict__ A, const float* __restrict__ W,
                             const float* __restrict__ bias, const float* __restrict__ add,
                             float* __restrict__ C, int N, int K, int Mo, int relu)
{
    __shared__ __align__(16) float As[16][68];
    __shared__ __align__(16) float Bs[16][68];
    const int bm = blockIdx.y * 64;
    const int bn = blockIdx.x * 64;
    const int tid = threadIdx.x;
    const int tx = tid & 15, ty = tid >> 4;
    const int lc = tid & 15, lr = tid >> 4;

    float acc[4][4];
#pragma unroll
    for (int i = 0; i < 4; i++)
#pragma unroll
        for (int j = 0; j < 4; j++) acc[i][j] = 0.f;

    for (int k0 = 0; k0 < K; k0 += 16) {
#pragma unroll
        for (int i = 0; i < 4; i++) {
            int r = lr + i * 16;
            As[lc][r] = A[(size_t)(bm + r) * K + k0 + lc];
            int wr = bn + r;
            Bs[lc][r] = (wr < Mo) ? W[(size_t)wr * K + k0 + lc] : 0.f;
        }
        __syncthreads();
#pragma unroll
        for (int kk = 0; kk < 16; kk++) {
            float4 a4 = *reinterpret_cast<const float4*>(&As[kk][ty * 4]);
            float4 b4 = *reinterpret_cast<const float4*>(&Bs[kk][tx * 4]);
            float av[4] = {a4.x, a4.y, a4.z, a4.w};
            float bv[4] = {b4.x, b4.y, b4.z, b4.w};
#pragma unroll
            for (int i = 0; i < 4; i++)
#pragma unroll
                for (int j = 0; j < 4; j++) acc[i][j] += av[i] * bv[j];
        }
        __syncthreads();
    }
#pragma unroll
    for (int i = 0; i < 4; i++) {
        int row = bm + ty * 4 + i;
#pragma unroll
        for (int j = 0; j < 4; j++) {
            int col = bn + tx * 4 + j;
            if (col < Mo) {
                float v = acc[i][j] + bias[col];
                if (add)  v += add[(size_t)row * Mo + col];
                if (relu) v = fmaxf(v, 0.f);
                C[(size_t)row * Mo + col] = v;
            }
        }
    }
}

// ---------------- im2col for 16x16/stride16 conv ----------------
__global__ void im2col_kernel(const float* __restrict__ x, float* __restrict__ out)
{
    int o = blockIdx.x * 256 + threadIdx.x;
    if (o >= NP_ * 768) return;
    int kk = o % 768;
    int t  = o / 768;
    int b = t / 196, p = t % 196;
    int gh = p / 14, gw = p % 14;
    int c = kk / 256, r = kk % 256;
    int pp = r / 16, qq = r % 16;
    out[o] = x[((size_t)(b * 3 + c) * 224 + gh * 16 + pp) * 224 + gw * 16 + qq];
}

// ---------------- LayerNorm helpers (192 threads/block) ----------------
__device__ __forceinline__ void block_stats192(float x, float* sh, float& mu, float& rs)
{
    float s = x, ss = x * x;
#pragma unroll
    for (int o = 16; o; o >>= 1) {
        s  += __shfl_down_sync(0xffffffffu, s,  o);
        ss += __shfl_down_sync(0xffffffffu, ss, o);
    }
    int w = threadIdx.x >> 5;
    if ((threadIdx.x & 31) == 0) { sh[w] = s; sh[6 + w] = ss; }
    __syncthreads();
    if (threadIdx.x == 0) {
        float a = 0.f, b = 0.f;
        for (int i = 0; i < 6; i++) { a += sh[i]; b += sh[6 + i]; }
        float m = a * (1.f / 192.f);
        float v = b * (1.f / 192.f) - m * m;
        sh[0] = m; sh[1] = rsqrtf(v + 1e-5f);
    }
    __syncthreads();
    mu = sh[0]; rs = sh[1];
}

__global__ void ln_kernel(const float* __restrict__ X, const float* __restrict__ g,
                          const float* __restrict__ bb, float* __restrict__ Y)
{
    int row = blockIdx.x, tid = threadIdx.x;
    __shared__ float sh[12];
    float x = X[(size_t)row * D_ + tid];
    float mu, rs;
    block_stats192(x, sh, mu, rs);
    Y[(size_t)row * D_ + tid] = (x - mu) * rs * g[tid] + bb[tid];
}

__global__ void dln_kernel(const float* __restrict__ X,
                           const float* __restrict__ g1, const float* __restrict__ b1,
                           const float* __restrict__ g2, const float* __restrict__ b2,
                           float* __restrict__ Y)
{
    int row = blockIdx.x, tid = threadIdx.x;
    __shared__ float sh[12];
    float x = X[(size_t)row * D_ + tid];
    float mu, rs;
    block_stats192(x, sh, mu, rs);
    float y = (x - mu) * rs * g1[tid] + b1[tid];
    __syncthreads();
    block_stats192(y, sh, mu, rs);
    Y[(size_t)row * D_ + tid] = (y - mu) * rs * g2[tid] + b2[tid];
}

__global__ void ln_patch_kernel(const float* __restrict__ T, const float* __restrict__ g,
                                const float* __restrict__ bb, const float* __restrict__ pos,
                                float* __restrict__ XC)
{
    int row = blockIdx.x, tid = threadIdx.x;   // row in [0, NP_)
    __shared__ float sh[12];
    float x = T[(size_t)row * D_ + tid];
    float mu, rs;
    block_stats192(x, sh, mu, rs);
    int b = row / 196, p = row % 196;
    float v = (x - mu) * rs * g[tid] + bb[tid] + pos[(size_t)(1 + p) * D_ + tid];
    XC[((size_t)b * L_ + 1 + p) * D_ + tid] = v;
}

__global__ void cls_kernel(const float* __restrict__ cls, const float* __restrict__ pos,
                           float* __restrict__ XC)
{
    int b = blockIdx.x, tid = threadIdx.x;
    XC[(size_t)b * L_ * D_ + tid] = cls[tid] + pos[tid];
}

// ---------------- FAVOR+ feature map ----------------
// X: [NT, D] (head-major rows). Phi: [NT, H*2M]. omega: [64,128] (this layer).
__global__ void favor_kernel(const float* __restrict__ X, const float* __restrict__ om,
                             float* __restrict__ Phi)
{
    int t = blockIdx.x, h = blockIdx.y, tid = threadIdx.x;  // 128 threads
    __shared__ float xs[64];
    __shared__ float offs;
    if (tid < 64) xs[tid] = X[(size_t)t * D_ + h * DH_ + tid] * 0.35355339059327373f;
    __syncthreads();
    if (tid < 32) {
        float a = xs[tid], b = xs[tid + 32];
        float s = a * a + b * b;
#pragma unroll
        for (int o = 16; o; o >>= 1) s += __shfl_down_sync(0xffffffffu, s, o);
        if (tid == 0) offs = 0.5f * s;
    }
    __syncthreads();
    float u = 0.f;
#pragma unroll
    for (int d = 0; d < 64; d++) u += xs[d] * om[d * MM_ + tid];
    float off = offs;
    float e1 = expf(u - off)  * 0.0625f;
    float e2 = expf(-u - off) * 0.0625f;
    size_t base = (size_t)t * (H_ * TM_) + h * TM_;
    Phi[base + tid]       = e1;
    Phi[base + MM_ + tid] = e2;
}

// ---------------- KV = Kp^T @ V per (b,h), plus Ksum ----------------
__global__ void kv_kernel(const float* __restrict__ Kp, const float* __restrict__ V,
                          float* __restrict__ KV, float* __restrict__ Ks)
{
    int b = blockIdx.x, h = blockIdx.y, m = threadIdx.x;  // 256 threads
    __shared__ float vs[64];
    float acc[64];
#pragma unroll
    for (int d = 0; d < 64; d++) acc[d] = 0.f;
    float ks = 0.f;
    for (int l = 0; l < L_; l++) {
        int t = b * L_ + l;
        if (m < 64) vs[m] = V[(size_t)t * D_ + h * DH_ + m];
        __syncthreads();
        float kp = Kp[(size_t)t * (H_ * TM_) + h * TM_ + m];
        ks += kp;
#pragma unroll
        for (int d = 0; d < 64; d++) acc[d] += kp * vs[d];
        __syncthreads();
    }
    size_t base = ((size_t)(b * H_ + h) * TM_ + m) * DH_;
#pragma unroll
    for (int d = 0; d < 64; d++) KV[base + d] = acc[d];
    Ks[(size_t)(b * H_ + h) * TM_ + m] = ks;
}

// ---------------- attn = Z * (Qp @ KV) per token ----------------
__global__ void attn_kernel(const float* __restrict__ Qp, const float* __restrict__ KV,
                            const float* __restrict__ Ks, float* __restrict__ O)
{
    int t = blockIdx.x, tid = threadIdx.x;   // 192 threads
    int b = t / L_;
    int h = tid >> 6, d = tid & 63;
    __shared__ float qs[768];
    __shared__ float zp[192];
    __shared__ float zsh[3];
#pragma unroll
    for (int j = 0; j < 4; j++) qs[tid + j * 192] = Qp[(size_t)t * 768 + tid + j * 192];
    __syncthreads();
    int bh = b * H_ + h;
    const float* ksr = Ks + (size_t)bh * TM_;
    const float* qh  = qs + h * TM_;
    float p = 0.f;
#pragma unroll
    for (int j = 0; j < 4; j++) p += qh[d * 4 + j] * ksr[d * 4 + j];
    zp[tid] = p;
    __syncthreads();
    if (d == 0) {
        float s = 0.f;
        for (int i = 0; i < 64; i++) s += zp[h * 64 + i];
        zsh[h] = 1.f / (s + 1e-6f);
    }
    __syncthreads();
    const float* kvb = KV + (size_t)bh * TM_ * DH_;
    float acc = 0.f;
#pragma unroll 8
    for (int mm = 0; mm < TM_; mm++) acc += qh[mm] * kvb[mm * DH_ + d];
    O[(size_t)t * D_ + tid] = acc * zsh[h];
}

// ---------------- mean pool over sequence ----------------
__global__ void pool_kernel(const float* __restrict__ XC, float* __restrict__ P)
{
    int b = blockIdx.x, tid = threadIdx.x;
    float s = 0.f;
    for (int l = 0; l < L_; l++) s += XC[((size_t)b * L_ + l) * D_ + tid];
    P[(size_t)b * D_ + tid] = s * (1.f / 197.f);
}

// ---------------- launcher ----------------
extern "C" void kernel_launch(void* const* d_in, const int* in_sizes, int n_in,
                              void* d_out, int out_size)
{
    (void)in_sizes; (void)n_in; (void)out_size;
    const float* x    = (const float*)d_in[0];
    const float* pw   = (const float*)d_in[1];
    const float* pb   = (const float*)d_in[2];
    const float* peg  = (const float*)d_in[3];
    const float* peb  = (const float*)d_in[4];
    const float* cls  = (const float*)d_in[5];
    const float* pos  = (const float*)d_in[6];
    const float* Wq   = (const float*)d_in[7];
    const float* bq   = (const float*)d_in[8];
    const float* Wk   = (const float*)d_in[9];
    const float* bk   = (const float*)d_in[10];
    const float* Wv   = (const float*)d_in[11];
    const float* bv   = (const float*)d_in[12];
    const float* Wo   = (const float*)d_in[13];
    const float* bo   = (const float*)d_in[14];
    const float* l1g  = (const float*)d_in[15];
    const float* l1b  = (const float*)d_in[16];
    const float* l2g  = (const float*)d_in[17];
    const float* l2b  = (const float*)d_in[18];
    const float* lbg  = (const float*)d_in[19];
    const float* lbb  = (const float*)d_in[20];
    const float* W1   = (const float*)d_in[21];
    const float* b1   = (const float*)d_in[22];
    const float* W2   = (const float*)d_in[23];
    const float* b2   = (const float*)d_in[24];
    const float* om   = (const float*)d_in[25];
    const float* hw   = (const float*)d_in[26];
    const float* hb   = (const float*)d_in[27];
    float* out = (float*)d_out;

    float *xc, *q, *k, *v, *Qp, *Kp, *KV, *Ks, *at, *tp, *h1, *pl, *im;
    cudaGetSymbolAddress((void**)&xc, g_xc);
    cudaGetSymbolAddress((void**)&q,  g_q);
    cudaGetSymbolAddress((void**)&k,  g_k);
    cudaGetSymbolAddress((void**)&v,  g_v);
    cudaGetSymbolAddress((void**)&Qp, g_Qp);
    cudaGetSymbolAddress((void**)&Kp, g_Kp);
    cudaGetSymbolAddress((void**)&KV, g_KV);
    cudaGetSymbolAddress((void**)&Ks, g_Ks);
    cudaGetSymbolAddress((void**)&at, g_at);
    cudaGetSymbolAddress((void**)&tp, g_tp);
    cudaGetSymbolAddress((void**)&h1, g_h1);
    cudaGetSymbolAddress((void**)&pl, g_pl);
    cudaGetSymbolAddress((void**)&im, g_im);

    // ---- patch embedding: im2col + GEMM + LN + pos, cls token ----
    {
        int tot = NP_ * 768;
        im2col_kernel<<<(tot + 255) / 256, 256>>>(x, im);
        sgemm_kernel<<<dim3(3, NP_ / 64), 256>>>(im, pw, pb, nullptr, q, NP_, 768, D_, 0);
        ln_patch_kernel<<<NP_, 192>>>(q, peg, peb, pos, xc);
        cls_kernel<<<B_, 192>>>(cls, pos, xc);
    }

    const dim3 gD(3, NT_ / 64);     // Mo=192
    const dim3 gF(12, NT_ / 64);    // Mo=768

    for (int i = 0; i < 12; i++) {
        const float* om_i = om + (size_t)i * DH_ * MM_;
        sgemm_kernel<<<gD, 256>>>(xc, Wq + (size_t)i * D_ * D_, bq + i * D_, nullptr, q, NT_, D_, D_, 0);
        sgemm_kernel<<<gD, 256>>>(xc, Wk + (size_t)i * D_ * D_, bk + i * D_, nullptr, k, NT_, D_, D_, 0);
        sgemm_kernel<<<gD, 256>>>(xc, Wv + (size_t)i * D_ * D_, bv + i * D_, nullptr, v, NT_, D_, D_, 0);
        favor_kernel<<<dim3(NT_, H_), 128>>>(q, om_i, Qp);
        favor_kernel<<<dim3(NT_, H_), 128>>>(k, om_i, Kp);
        kv_kernel<<<dim3(B_, H_), 256>>>(Kp, v, KV, Ks);
        attn_kernel<<<NT_, 192>>>(Qp, KV, Ks, at);
        // xc_new_pre = xc + attn @ Wo^T + bo
        sgemm_kernel<<<gD, 256>>>(at, Wo + (size_t)i * D_ * D_, bo + i * D_, xc, tp, NT_, D_, D_, 0);
        ln_kernel<<<NT_, 192>>>(tp, l1g + i * D_, l1b + i * D_, xc);
        // MLP
        sgemm_kernel<<<gF, 256>>>(xc, W1 + (size_t)i * FF_ * D_, b1 + i * FF_, nullptr, h1, NT_, D_, FF_, 1);
        sgemm_kernel<<<gD, 256>>>(h1, W2 + (size_t)i * D_ * FF_, b2 + i * D_, xc, tp, NT_, FF_, D_, 0);
        dln_kernel<<<NT_, 192>>>(tp, l2g + i * D_, l2b + i * D_, lbg + i * D_, lbb + i * D_, xc);

        if (i == 3 || i == 7 || i == 11) {
            int j = (i == 3) ? 0 : (i == 7) ? 1 : 2;
            pool_kernel<<<B_, 192>>>(xc, pl);
            sgemm_kernel<<<dim3(16, 1), 256>>>(pl, hw + (size_t)j * NCLS_ * D_, hb + j * NCLS_,
                                               nullptr, out + (size_t)j * B_ * NCLS_, B_, D_, NCLS_, 0);
        }
    }
}

// round 5
// speedup vs baseline: 1.0031x; 1.0031x over previous
#include <cuda_runtime.h>
#include <math.h>

#define B_    64
#define L_    197
#define D_    192
#define H_    3
#define DH_   64
#define MM_   128
#define TM_   256           // 2M
#define NT_   (B_*L_)       // 12608
#define FF_   768
#define NCLS_ 1000
#define NP_   (B_*196)      // 12544

// ---------------- scratch (static device globals; no allocation) ----------------
__device__ float g_xc[NT_*D_];
__device__ float g_q [NT_*D_];
__device__ float g_k [NT_*D_];
__device__ float g_v [NT_*D_];
__device__ float g_Qp[NT_*H_*TM_];
__device__ float g_Kp[NT_*H_*TM_];
__device__ float g_KV[B_*H_*TM_*DH_];
__device__ float g_Ks[B_*H_*TM_];
__device__ float g_at[NT_*D_];
__device__ float g_tp[NT_*D_];
__device__ float g_h1[NT_*FF_];
__device__ float g_pl[B_*D_];
__device__ float g_im[NP_*768];

// ---------------- GEMM: C[N,Mo] = A[N,K] @ W[Mo,K]^T (+bias, +add, relu) --------
// 64x64 tile, BK=16, 256 threads, 4x4 register blocking. N must be multiple of 64,
// K multiple of 16. Mo arbitrary (col guards).
__global__ void sgemm_kernel(const float* __restrict__ A, const float* __restrict__ W,
                             const float* __restrict__ bias, const float* __restrict__ add,
                             float* __restrict__ C, int N, int K, int Mo, int relu)
{
    __shared__ __align__(16) float As[16][68];
    __shared__ __align__(16) float Bs[16][68];
    const int bm = blockIdx.y * 64;
    const int bn = blockIdx.x * 64;
    const int tid = threadIdx.x;
    const int tx = tid & 15, ty = tid >> 4;
    const int lc = tid & 15, lr = tid >> 4;

    float acc[4][4];
#pragma unroll
    for (int i = 0; i < 4; i++)
#pragma unroll
        for (int j = 0; j < 4; j++) acc[i][j] = 0.f;

    for (int k0 = 0; k0 < K; k0 += 16) {
#pragma unroll
        for (int i = 0; i < 4; i++) {
            int r = lr + i * 16;
            As[lc][r] = A[(size_t)(bm + r) * K + k0 + lc];
            int wr = bn + r;
            Bs[lc][r] = (wr < Mo) ? W[(size_t)wr * K + k0 + lc] : 0.f;
        }
        __syncthreads();
#pragma unroll
        for (int kk = 0; kk < 16; kk++) {
            float4 a4 = *reinterpret_cast<const float4*>(&As[kk][ty * 4]);
            float4 b4 = *reinterpret_cast<const float4*>(&Bs[kk][tx * 4]);
            float av[4] = {a4.x, a4.y, a4.z, a4.w};
            float bv[4] = {b4.x, b4.y, b4.z, b4.w};
#pragma unroll
            for (int i = 0; i < 4; i++)
#pragma unroll
                for (int j = 0; j < 4; j++) acc[i][j] += av[i] * bv[j];
        }
        __syncthreads();
    }
#pragma unroll
    for (int i = 0; i < 4; i++) {
        int row = bm + ty * 4 + i;
#pragma unroll
        for (int j = 0; j < 4; j++) {
            int col = bn + tx * 4 + j;
            if (col < Mo) {
                float v = acc[i][j] + bias[col];
                if (add)  v += add[(size_t)row * Mo + col];
                if (relu) v = fmaxf(v, 0.f);
                C[(size_t)row * Mo + col] = v;
            }
        }
    }
}

// ---------------- im2col for 16x16/stride16 conv ----------------
__global__ void im2col_kernel(const float* __restrict__ x, float* __restrict__ out)
{
    int o = blockIdx.x * 256 + threadIdx.x;
    if (o >= NP_ * 768) return;
    int kk = o % 768;
    int t  = o / 768;
    int b = t / 196, p = t % 196;
    int gh = p / 14, gw = p % 14;
    int c = kk / 256, r = kk % 256;
    int pp = r / 16, qq = r % 16;
    out[o] = x[((size_t)(b * 3 + c) * 224 + gh * 16 + pp) * 224 + gw * 16 + qq];
}

// ---------------- LayerNorm helpers (192 threads/block) ----------------
__device__ __forceinline__ void block_stats192(float x, float* sh, float& mu, float& rs)
{
    float s = x, ss = x * x;
#pragma unroll
    for (int o = 16; o; o >>= 1) {
        s  += __shfl_down_sync(0xffffffffu, s,  o);
        ss += __shfl_down_sync(0xffffffffu, ss, o);
    }
    int w = threadIdx.x >> 5;
    if ((threadIdx.x & 31) == 0) { sh[w] = s; sh[6 + w] = ss; }
    __syncthreads();
    if (threadIdx.x == 0) {
        float a = 0.f, b = 0.f;
        for (int i = 0; i < 6; i++) { a += sh[i]; b += sh[6 + i]; }
        float m = a * (1.f / 192.f);
        float v = b * (1.f / 192.f) - m * m;
        sh[0] = m; sh[1] = rsqrtf(v + 1e-5f);
    }
    __syncthreads();
    mu = sh[0]; rs = sh[1];
}

__global__ void ln_kernel(const float* __restrict__ X, const float* __restrict__ g,
                          const float* __restrict__ bb, float* __restrict__ Y)
{
    int row = blockIdx.x, tid = threadIdx.x;
    __shared__ float sh[12];
    float x = X[(size_t)row * D_ + tid];
    float mu, rs;
    block_stats192(x, sh, mu, rs);
    Y[(size_t)row * D_ + tid] = (x - mu) * rs * g[tid] + bb[tid];
}

__global__ void dln_kernel(const float* __restrict__ X,
                           const float* __restrict__ g1, const float* __restrict__ b1,
                           const float* __restrict__ g2, const float* __restrict__ b2,
                           float* __restrict__ Y)
{
    int row = blockIdx.x, tid = threadIdx.x;
    __shared__ float sh[12];
    float x = X[(size_t)row * D_ + tid];
    float mu, rs;
    block_stats192(x, sh, mu, rs);
    float y = (x - mu) * rs * g1[tid] + b1[tid];
    __syncthreads();
    block_stats192(y, sh, mu, rs);
    Y[(size_t)row * D_ + tid] = (y - mu) * rs * g2[tid] + b2[tid];
}

__global__ void ln_patch_kernel(const float* __restrict__ T, const float* __restrict__ g,
                                const float* __restrict__ bb, const float* __restrict__ pos,
                                float* __restrict__ XC)
{
    int row = blockIdx.x, tid = threadIdx.x;   // row in [0, NP_)
    __shared__ float sh[12];
    float x = T[(size_t)row * D_ + tid];
    float mu, rs;
    block_stats192(x, sh, mu, rs);
    int b = row / 196, p = row % 196;
    float v = (x - mu) * rs * g[tid] + bb[tid] + pos[(size_t)(1 + p) * D_ + tid];
    XC[((size_t)b * L_ + 1 + p) * D_ + tid] = v;
}

__global__ void cls_kernel(const float* __restrict__ cls, const float* __restrict__ pos,
                           float* __restrict__ XC)
{
    int b = blockIdx.x, tid = threadIdx.x;
    XC[(size_t)b * L_ * D_ + tid] = cls[tid] + pos[tid];
}

// ---------------- FAVOR+ feature map ----------------
// X: [NT, D] (head-major rows). Phi: [NT, H*2M]. omega: [64,128] (this layer).
__global__ void favor_kernel(const float* __restrict__ X, const float* __restrict__ om,
                             float* __restrict__ Phi)
{
    int t = blockIdx.x, h = blockIdx.y, tid = threadIdx.x;  // 128 threads
    __shared__ float xs[64];
    __shared__ float offs;
    if (tid < 64) xs[tid] = X[(size_t)t * D_ + h * DH_ + tid] * 0.35355339059327373f;
    __syncthreads();
    if (tid < 32) {
        float a = xs[tid], b = xs[tid + 32];
        float s = a * a + b * b;
#pragma unroll
        for (int o = 16; o; o >>= 1) s += __shfl_down_sync(0xffffffffu, s, o);
        if (tid == 0) offs = 0.5f * s;
    }
    __syncthreads();
    float u = 0.f;
#pragma unroll
    for (int d = 0; d < 64; d++) u += xs[d] * om[d * MM_ + tid];
    float off = offs;
    float e1 = expf(u - off)  * 0.0625f;
    float e2 = expf(-u - off) * 0.0625f;
    size_t base = (size_t)t * (H_ * TM_) + h * TM_;
    Phi[base + tid]       = e1;
    Phi[base + MM_ + tid] = e2;
}

// ---------------- KV = Kp^T @ V per (b,h), plus Ksum ----------------
__global__ void kv_kernel(const float* __restrict__ Kp, const float* __restrict__ V,
                          float* __restrict__ KV, float* __restrict__ Ks)
{
    int b = blockIdx.x, h = blockIdx.y, m = threadIdx.x;  // 256 threads
    __shared__ float vs[64];
    float acc[64];
#pragma unroll
    for (int d = 0; d < 64; d++) acc[d] = 0.f;
    float ks = 0.f;
    for (int l = 0; l < L_; l++) {
        int t = b * L_ + l;
        if (m < 64) vs[m] = V[(size_t)t * D_ + h * DH_ + m];
        __syncthreads();
        float kp = Kp[(size_t)t * (H_ * TM_) + h * TM_ + m];
        ks += kp;
#pragma unroll
        for (int d = 0; d < 64; d++) acc[d] += kp * vs[d];
        __syncthreads();
    }
    size_t base = ((size_t)(b * H_ + h) * TM_ + m) * DH_;
#pragma unroll
    for (int d = 0; d < 64; d++) KV[base + d] = acc[d];
    Ks[(size_t)(b * H_ + h) * TM_ + m] = ks;
}

// ---------------- attn = Z * (Qp @ KV) per token ----------------
__global__ void attn_kernel(const float* __restrict__ Qp, const float* __restrict__ KV,
                            const float* __restrict__ Ks, float* __restrict__ O)
{
    int t = blockIdx.x, tid = threadIdx.x;   // 192 threads
    int b = t / L_;
    int h = tid >> 6, d = tid & 63;
    __shared__ float qs[768];
    __shared__ float zp[192];
    __shared__ float zsh[3];
#pragma unroll
    for (int j = 0; j < 4; j++) qs[tid + j * 192] = Qp[(size_t)t * 768 + tid + j * 192];
    __syncthreads();
    int bh = b * H_ + h;
    const float* ksr = Ks + (size_t)bh * TM_;
    const float* qh  = qs + h * TM_;
    float p = 0.f;
#pragma unroll
    for (int j = 0; j < 4; j++) p += qh[d * 4 + j] * ksr[d * 4 + j];
    zp[tid] = p;
    __syncthreads();
    if (d == 0) {
        float s = 0.f;
        for (int i = 0; i < 64; i++) s += zp[h * 64 + i];
        zsh[h] = 1.f / (s + 1e-6f);
    }
    __syncthreads();
    const float* kvb = KV + (size_t)bh * TM_ * DH_;
    float acc = 0.f;
#pragma unroll 8
    for (int mm = 0; mm < TM_; mm++) acc += qh[mm] * kvb[mm * DH_ + d];
    O[(size_t)t * D_ + tid] = acc * zsh[h];
}

// ---------------- mean pool over sequence ----------------
__global__ void pool_kernel(const float* __restrict__ XC, float* __restrict__ P)
{
    int b = blockIdx.x, tid = threadIdx.x;
    float s = 0.f;
    for (int l = 0; l < L_; l++) s += XC[((size_t)b * L_ + l) * D_ + tid];
    P[(size_t)b * D_ + tid] = s * (1.f / 197.f);
}

// ---------------- launcher ----------------
extern "C" void kernel_launch(void* const* d_in, const int* in_sizes, int n_in,
                              void* d_out, int out_size)
{
    (void)in_sizes; (void)n_in; (void)out_size;
    const float* x    = (const float*)d_in[0];
    const float* pw   = (const float*)d_in[1];
    const float* pb   = (const float*)d_in[2];
    const float* peg  = (const float*)d_in[3];
    const float* peb  = (const float*)d_in[4];
    const float* cls  = (const float*)d_in[5];
    const float* pos  = (const float*)d_in[6];
    const float* Wq   = (const float*)d_in[7];
    const float* bq   = (const float*)d_in[8];
    const float* Wk   = (const float*)d_in[9];
    const float* bk   = (const float*)d_in[10];
    const float* Wv   = (const float*)d_in[11];
    const float* bv   = (const float*)d_in[12];
    const float* Wo   = (const float*)d_in[13];
    const float* bo   = (const float*)d_in[14];
    const float* l1g  = (const float*)d_in[15];
    const float* l1b  = (const float*)d_in[16];
    const float* l2g  = (const float*)d_in[17];
    const float* l2b  = (const float*)d_in[18];
    const float* lbg  = (const float*)d_in[19];
    const float* lbb  = (const float*)d_in[20];
    const float* W1   = (const float*)d_in[21];
    const float* b1   = (const float*)d_in[22];
    const float* W2   = (const float*)d_in[23];
    const float* b2   = (const float*)d_in[24];
    const float* om   = (const float*)d_in[25];
    const float* hw   = (const float*)d_in[26];
    const float* hb   = (const float*)d_in[27];
    float* out = (float*)d_out;

    float *xc, *q, *k, *v, *Qp, *Kp, *KV, *Ks, *at, *tp, *h1, *pl, *im;
    cudaGetSymbolAddress((void**)&xc, g_xc);
    cudaGetSymbolAddress((void**)&q,  g_q);
    cudaGetSymbolAddress((void**)&k,  g_k);
    cudaGetSymbolAddress((void**)&v,  g_v);
    cudaGetSymbolAddress((void**)&Qp, g_Qp);
    cudaGetSymbolAddress((void**)&Kp, g_Kp);
    cudaGetSymbolAddress((void**)&KV, g_KV);
    cudaGetSymbolAddress((void**)&Ks, g_Ks);
    cudaGetSymbolAddress((void**)&at, g_at);
    cudaGetSymbolAddress((void**)&tp, g_tp);
    cudaGetSymbolAddress((void**)&h1, g_h1);
    cudaGetSymbolAddress((void**)&pl, g_pl);
    cudaGetSymbolAddress((void**)&im, g_im);

    // ---- patch embedding: im2col + GEMM + LN + pos, cls token ----
    {
        int tot = NP_ * 768;
        im2col_kernel<<<(tot + 255) / 256, 256>>>(x, im);
        sgemm_kernel<<<dim3(3, NP_ / 64), 256>>>(im, pw, pb, nullptr, q, NP_, 768, D_, 0);
        ln_patch_kernel<<<NP_, 192>>>(q, peg, peb, pos, xc);
        cls_kernel<<<B_, 192>>>(cls, pos, xc);
    }

    const dim3 gD(3, NT_ / 64);     // Mo=192
    const dim3 gF(12, NT_ / 64);    // Mo=768

    for (int i = 0; i < 12; i++) {
        const float* om_i = om + (size_t)i * DH_ * MM_;
        sgemm_kernel<<<gD, 256>>>(xc, Wq + (size_t)i * D_ * D_, bq + i * D_, nullptr, q, NT_, D_, D_, 0);
        sgemm_kernel<<<gD, 256>>>(xc, Wk + (size_t)i * D_ * D_, bk + i * D_, nullptr, k, NT_, D_, D_, 0);
        sgemm_kernel<<<gD, 256>>>(xc, Wv + (size_t)i * D_ * D_, bv + i * D_, nullptr, v, NT_, D_, D_, 0);
        favor_kernel<<<dim3(NT_, H_), 128>>>(q, om_i, Qp);
        favor_kernel<<<dim3(NT_, H_), 128>>>(k, om_i, Kp);
        kv_kernel<<<dim3(B_, H_), 256>>>(Kp, v, KV, Ks);
        attn_kernel<<<NT_, 192>>>(Qp, KV, Ks, at);
        // xc_new_pre = xc + attn @ Wo^T + bo
        sgemm_kernel<<<gD, 256>>>(at, Wo + (size_t)i * D_ * D_, bo + i * D_, xc, tp, NT_, D_, D_, 0);
        ln_kernel<<<NT_, 192>>>(tp, l1g + i * D_, l1b + i * D_, xc);
        // MLP
        sgemm_kernel<<<gF, 256>>>(xc, W1 + (size_t)i * FF_ * D_, b1 + i * FF_, nullptr, h1, NT_, D_, FF_, 1);
        sgemm_kernel<<<gD, 256>>>(h1, W2 + (size_t)i * D_ * FF_, b2 + i * D_, xc, tp, NT_, FF_, D_, 0);
        dln_kernel<<<NT_, 192>>>(tp, l2g + i * D_, l2b + i * D_, lbg + i * D_, lbb + i * D_, xc);

        if (i == 3 || i == 7 || i == 11) {
            int j = (i == 3) ? 0 : (i == 7) ? 1 : 2;
            pool_kernel<<<B_, 192>>>(xc, pl);
            sgemm_kernel<<<dim3(16, 1), 256>>>(pl, hw + (size_t)j * NCLS_ * D_, hb + j * NCLS_,
                                               nullptr, out + (size_t)j * B_ * NCLS_, B_, D_, NCLS_, 0);
        }
    }
}

// round 6
// speedup vs baseline: 1.6242x; 1.6192x over previous
#include <cuda_runtime.h>
#include <math.h>
#include <stdint.h>

#define B_    64
#define L_    197
#define D_    192
#define H_    3
#define DH_   64
#define MM_   128
#define TM_   256           // 2M
#define NT_   (B_*L_)       // 12608
#define NTP_  12672         // 99 * 128 (padded rows)
#define FF_   768
#define NCLS_ 1000
#define NP_   (B_*196)      // 12544

// ---------------- scratch (static device globals; zero-initialized) ----------------
__device__ float g_xc[NTP_*D_];
__device__ float g_q [NTP_*D_];
__device__ float g_k [NTP_*D_];
__device__ float g_v [NTP_*D_];
__device__ float g_Qp[NT_*H_*TM_];
__device__ float g_Kp[NT_*H_*TM_];
__device__ float g_KV[B_*H_*TM_*DH_];
__device__ float g_Ks[B_*H_*TM_];
__device__ float g_at[NTP_*D_];
__device__ float g_tp[NTP_*D_];
__device__ float g_h1[NTP_*FF_];
__device__ float g_pl[128*D_];
__device__ float g_im[NP_*768];

// ---------------- TF32 tensor-core GEMM ----------------
// C[N,Mo] = A[N,K] @ W[Mo,K]^T (+bias, +add, +relu)
// Block tile 128x64, BK=32, 256 threads (8 warps, 4x2 warp grid, 32x32 warp tile).
// Requires: K % 32 == 0; A rows available up to blockIdx.y*128+127 (padded buffers);
// stores guarded by row < Nstore and col < Mo.
__device__ __forceinline__ uint32_t f2tf(float f) {
    uint32_t o; asm("cvt.rna.tf32.f32 %0, %1;" : "=r"(o) : "f"(f)); return o;
}

__global__ __launch_bounds__(256) void tgemm_kernel(
    const float* __restrict__ A, const float* __restrict__ W,
    const float* __restrict__ bias, const float* __restrict__ add,
    float* __restrict__ C, int K, int Mo, int Nstore, int relu)
{
    __shared__ __align__(16) uint32_t As[128*36];
    __shared__ __align__(16) uint32_t Ws[64*36];
    const int bm = blockIdx.y * 128;
    const int bn = blockIdx.x * 64;
    const int tid  = threadIdx.x;
    const int lane = tid & 31, wid = tid >> 5;
    const int warp_m = wid >> 1, warp_n = wid & 1;
    const int gid = lane >> 2, tg = lane & 3;

    float acc[2][4][4];
#pragma unroll
    for (int a = 0; a < 2; a++)
#pragma unroll
        for (int b = 0; b < 4; b++)
#pragma unroll
            for (int c = 0; c < 4; c++) acc[a][b][c] = 0.f;

    const int niter = K >> 5;
    float4 pa[4], pw[2];

    // prefetch tile 0
#pragma unroll
    for (int p = 0; p < 4; p++) {
        int idx = tid + p * 256;
        int r = idx >> 3, c = (idx & 7) << 2;
        pa[p] = *reinterpret_cast<const float4*>(A + (size_t)(bm + r) * K + c);
    }
#pragma unroll
    for (int p = 0; p < 2; p++) {
        int idx = tid + p * 256;
        int r = idx >> 3, c = (idx & 7) << 2;
        int wr = bn + r;
        pw[p] = (wr < Mo) ? *reinterpret_cast<const float4*>(W + (size_t)wr * K + c)
                          : make_float4(0.f, 0.f, 0.f, 0.f);
    }

    for (int it = 0; it < niter; it++) {
        // regs -> smem (cvt to tf32)
#pragma unroll
        for (int p = 0; p < 4; p++) {
            int idx = tid + p * 256;
            int r = idx >> 3, c = (idx & 7) << 2;
            uint32_t* d = &As[r * 36 + c];
            d[0] = f2tf(pa[p].x); d[1] = f2tf(pa[p].y);
            d[2] = f2tf(pa[p].z); d[3] = f2tf(pa[p].w);
        }
#pragma unroll
        for (int p = 0; p < 2; p++) {
            int idx = tid + p * 256;
            int r = idx >> 3, c = (idx & 7) << 2;
            uint32_t* d = &Ws[r * 36 + c];
            d[0] = f2tf(pw[p].x); d[1] = f2tf(pw[p].y);
            d[2] = f2tf(pw[p].z); d[3] = f2tf(pw[p].w);
        }
        __syncthreads();

        // prefetch next tile
        if (it + 1 < niter) {
            int k0 = (it + 1) << 5;
#pragma unroll
            for (int p = 0; p < 4; p++) {
                int idx = tid + p * 256;
                int r = idx >> 3, c = (idx & 7) << 2;
                pa[p] = *reinterpret_cast<const float4*>(A + (size_t)(bm + r) * K + k0 + c);
            }
#pragma unroll
            for (int p = 0; p < 2; p++) {
                int idx = tid + p * 256;
                int r = idx >> 3, c = (idx & 7) << 2;
                int wr = bn + r;
                pw[p] = (wr < Mo) ? *reinterpret_cast<const float4*>(W + (size_t)wr * K + k0 + c)
                                  : make_float4(0.f, 0.f, 0.f, 0.f);
            }
        }

        // compute BK=32 as 4 k-steps of 8
#pragma unroll
        for (int ks = 0; ks < 4; ks++) {
            const int kb = ks * 8;
            uint32_t af[2][4], bf[4][2];
#pragma unroll
            for (int fm = 0; fm < 2; fm++) {
                int r0 = warp_m * 32 + fm * 16 + gid;
                af[fm][0] = As[r0 * 36 + kb + tg];
                af[fm][1] = As[(r0 + 8) * 36 + kb + tg];
                af[fm][2] = As[r0 * 36 + kb + tg + 4];
                af[fm][3] = As[(r0 + 8) * 36 + kb + tg + 4];
            }
#pragma unroll
            for (int fn = 0; fn < 4; fn++) {
                int n = warp_n * 32 + fn * 8 + gid;
                bf[fn][0] = Ws[n * 36 + kb + tg];
                bf[fn][1] = Ws[n * 36 + kb + tg + 4];
            }
#pragma unroll
            for (int fm = 0; fm < 2; fm++)
#pragma unroll
                for (int fn = 0; fn < 4; fn++) {
                    asm volatile(
                        "mma.sync.aligned.m16n8k8.row.col.f32.tf32.tf32.f32 "
                        "{%0,%1,%2,%3}, {%4,%5,%6,%7}, {%8,%9}, {%0,%1,%2,%3};\n"
                        : "+f"(acc[fm][fn][0]), "+f"(acc[fm][fn][1]),
                          "+f"(acc[fm][fn][2]), "+f"(acc[fm][fn][3])
                        : "r"(af[fm][0]), "r"(af[fm][1]), "r"(af[fm][2]), "r"(af[fm][3]),
                          "r"(bf[fn][0]), "r"(bf[fn][1]));
                }
        }
        __syncthreads();
    }

    // epilogue: bias + optional residual + optional relu
#pragma unroll
    for (int fm = 0; fm < 2; fm++) {
        int rbase = bm + warp_m * 32 + fm * 16 + gid;
#pragma unroll
        for (int fn = 0; fn < 4; fn++) {
            int c = bn + warp_n * 32 + fn * 8 + (tg << 1);
            if (c < Mo) {
                float bc0 = bias[c], bc1 = bias[c + 1];
#pragma unroll
                for (int h = 0; h < 2; h++) {
                    int row = rbase + h * 8;
                    if (row < Nstore) {
                        float v0 = acc[fm][fn][h * 2 + 0] + bc0;
                        float v1 = acc[fm][fn][h * 2 + 1] + bc1;
                        if (add) {
                            float2 ad = *reinterpret_cast<const float2*>(add + (size_t)row * Mo + c);
                            v0 += ad.x; v1 += ad.y;
                        }
                        if (relu) { v0 = fmaxf(v0, 0.f); v1 = fmaxf(v1, 0.f); }
                        *reinterpret_cast<float2*>(C + (size_t)row * Mo + c) = make_float2(v0, v1);
                    }
                }
            }
        }
    }
}

// ---------------- im2col for 16x16/stride16 conv ----------------
__global__ void im2col_kernel(const float* __restrict__ x, float* __restrict__ out)
{
    int o = blockIdx.x * 256 + threadIdx.x;
    if (o >= NP_ * 768) return;
    int kk = o % 768;
    int t  = o / 768;
    int b = t / 196, p = t % 196;
    int gh = p / 14, gw = p % 14;
    int c = kk / 256, r = kk % 256;
    int pp = r / 16, qq = r % 16;
    out[o] = x[((size_t)(b * 3 + c) * 224 + gh * 16 + pp) * 224 + gw * 16 + qq];
}

// ---------------- LayerNorm helpers (192 threads/block) ----------------
__device__ __forceinline__ void block_stats192(float x, float* sh, float& mu, float& rs)
{
    float s = x, ss = x * x;
#pragma unroll
    for (int o = 16; o; o >>= 1) {
        s  += __shfl_down_sync(0xffffffffu, s,  o);
        ss += __shfl_down_sync(0xffffffffu, ss, o);
    }
    int w = threadIdx.x >> 5;
    if ((threadIdx.x & 31) == 0) { sh[w] = s; sh[6 + w] = ss; }
    __syncthreads();
    if (threadIdx.x == 0) {
        float a = 0.f, b = 0.f;
        for (int i = 0; i < 6; i++) { a += sh[i]; b += sh[6 + i]; }
        float m = a * (1.f / 192.f);
        float v = b * (1.f / 192.f) - m * m;
        sh[0] = m; sh[1] = rsqrtf(v + 1e-5f);
    }
    __syncthreads();
    mu = sh[0]; rs = sh[1];
}

__global__ void ln_kernel(const float* __restrict__ X, const float* __restrict__ g,
                          const float* __restrict__ bb, float* __restrict__ Y)
{
    int row = blockIdx.x, tid = threadIdx.x;
    __shared__ float sh[12];
    float x = X[(size_t)row * D_ + tid];
    float mu, rs;
    block_stats192(x, sh, mu, rs);
    Y[(size_t)row * D_ + tid] = (x - mu) * rs * g[tid] + bb[tid];
}

__global__ void dln_kernel(const float* __restrict__ X,
                           const float* __restrict__ g1, const float* __restrict__ b1,
                           const float* __restrict__ g2, const float* __restrict__ b2,
                           float* __restrict__ Y)
{
    int row = blockIdx.x, tid = threadIdx.x;
    __shared__ float sh[12];
    float x = X[(size_t)row * D_ + tid];
    float mu, rs;
    block_stats192(x, sh, mu, rs);
    float y = (x - mu) * rs * g1[tid] + b1[tid];
    __syncthreads();
    block_stats192(y, sh, mu, rs);
    Y[(size_t)row * D_ + tid] = (y - mu) * rs * g2[tid] + b2[tid];
}

__global__ void ln_patch_kernel(const float* __restrict__ T, const float* __restrict__ g,
                                const float* __restrict__ bb, const float* __restrict__ pos,
                                float* __restrict__ XC)
{
    int row = blockIdx.x, tid = threadIdx.x;   // row in [0, NP_)
    __shared__ float sh[12];
    float x = T[(size_t)row * D_ + tid];
    float mu, rs;
    block_stats192(x, sh, mu, rs);
    int b = row / 196, p = row % 196;
    float v = (x - mu) * rs * g[tid] + bb[tid] + pos[(size_t)(1 + p) * D_ + tid];
    XC[((size_t)b * L_ + 1 + p) * D_ + tid] = v;
}

__global__ void cls_kernel(const float* __restrict__ cls, const float* __restrict__ pos,
                           float* __restrict__ XC)
{
    int b = blockIdx.x, tid = threadIdx.x;
    XC[(size_t)b * L_ * D_ + tid] = cls[tid] + pos[tid];
}

// ---------------- FAVOR+ feature map ----------------
__global__ void favor_kernel(const float* __restrict__ X, const float* __restrict__ om,
                             float* __restrict__ Phi)
{
    int t = blockIdx.x, h = blockIdx.y, tid = threadIdx.x;  // 128 threads
    __shared__ float xs[64];
    __shared__ float offs;
    if (tid < 64) xs[tid] = X[(size_t)t * D_ + h * DH_ + tid] * 0.35355339059327373f;
    __syncthreads();
    if (tid < 32) {
        float a = xs[tid], b = xs[tid + 32];
        float s = a * a + b * b;
#pragma unroll
        for (int o = 16; o; o >>= 1) s += __shfl_down_sync(0xffffffffu, s, o);
        if (tid == 0) offs = 0.5f * s;
    }
    __syncthreads();
    float u = 0.f;
#pragma unroll
    for (int d = 0; d < 64; d++) u += xs[d] * om[d * MM_ + tid];
    float off = offs;
    float e1 = expf(u - off)  * 0.0625f;
    float e2 = expf(-u - off) * 0.0625f;
    size_t base = (size_t)t * (H_ * TM_) + h * TM_;
    Phi[base + tid]       = e1;
    Phi[base + MM_ + tid] = e2;
}

// ---------------- KV = Kp^T @ V per (b,h), plus Ksum ----------------
__global__ void kv_kernel(const float* __restrict__ Kp, const float* __restrict__ V,
                          float* __restrict__ KV, float* __restrict__ Ks)
{
    int b = blockIdx.x, h = blockIdx.y, m = threadIdx.x;  // 256 threads
    __shared__ float vs[64];
    float acc[64];
#pragma unroll
    for (int d = 0; d < 64; d++) acc[d] = 0.f;
    float ks = 0.f;
    for (int l = 0; l < L_; l++) {
        int t = b * L_ + l;
        if (m < 64) vs[m] = V[(size_t)t * D_ + h * DH_ + m];
        __syncthreads();
        float kp = Kp[(size_t)t * (H_ * TM_) + h * TM_ + m];
        ks += kp;
#pragma unroll
        for (int d = 0; d < 64; d++) acc[d] += kp * vs[d];
        __syncthreads();
    }
    size_t base = ((size_t)(b * H_ + h) * TM_ + m) * DH_;
#pragma unroll
    for (int d = 0; d < 64; d++) KV[base + d] = acc[d];
    Ks[(size_t)(b * H_ + h) * TM_ + m] = ks;
}

// ---------------- attn = Z * (Qp @ KV) per token ----------------
__global__ void attn_kernel(const float* __restrict__ Qp, const float* __restrict__ KV,
                            const float* __restrict__ Ks, float* __restrict__ O)
{
    int t = blockIdx.x, tid = threadIdx.x;   // 192 threads
    int b = t / L_;
    int h = tid >> 6, d = tid & 63;
    __shared__ float qs[768];
    __shared__ float zp[192];
    __shared__ float zsh[3];
#pragma unroll
    for (int j = 0; j < 4; j++) qs[tid + j * 192] = Qp[(size_t)t * 768 + tid + j * 192];
    __syncthreads();
    int bh = b * H_ + h;
    const float* ksr = Ks + (size_t)bh * TM_;
    const float* qh  = qs + h * TM_;
    float p = 0.f;
#pragma unroll
    for (int j = 0; j < 4; j++) p += qh[d * 4 + j] * ksr[d * 4 + j];
    zp[tid] = p;
    __syncthreads();
    if (d == 0) {
        float s = 0.f;
        for (int i = 0; i < 64; i++) s += zp[h * 64 + i];
        zsh[h] = 1.f / (s + 1e-6f);
    }
    __syncthreads();
    const float* kvb = KV + (size_t)bh * TM_ * DH_;
    float acc = 0.f;
#pragma unroll 8
    for (int mm = 0; mm < TM_; mm++) acc += qh[mm] * kvb[mm * DH_ + d];
    O[(size_t)t * D_ + tid] = acc * zsh[h];
}

// ---------------- mean pool over sequence ----------------
__global__ void pool_kernel(const float* __restrict__ XC, float* __restrict__ P)
{
    int b = blockIdx.x, tid = threadIdx.x;
    float s = 0.f;
    for (int l = 0; l < L_; l++) s += XC[((size_t)b * L_ + l) * D_ + tid];
    P[(size_t)b * D_ + tid] = s * (1.f / 197.f);
}

// ---------------- launcher ----------------
extern "C" void kernel_launch(void* const* d_in, const int* in_sizes, int n_in,
                              void* d_out, int out_size)
{
    (void)in_sizes; (void)n_in; (void)out_size;
    const float* x    = (const float*)d_in[0];
    const float* pw   = (const float*)d_in[1];
    const float* pb   = (const float*)d_in[2];
    const float* peg  = (const float*)d_in[3];
    const float* peb  = (const float*)d_in[4];
    const float* cls  = (const float*)d_in[5];
    const float* pos  = (const float*)d_in[6];
    const float* Wq   = (const float*)d_in[7];
    const float* bq   = (const float*)d_in[8];
    const float* Wk   = (const float*)d_in[9];
    const float* bk   = (const float*)d_in[10];
    const float* Wv   = (const float*)d_in[11];
    const float* bv   = (const float*)d_in[12];
    const float* Wo   = (const float*)d_in[13];
    const float* bo   = (const float*)d_in[14];
    const float* l1g  = (const float*)d_in[15];
    const float* l1b  = (const float*)d_in[16];
    const float* l2g  = (const float*)d_in[17];
    const float* l2b  = (const float*)d_in[18];
    const float* lbg  = (const float*)d_in[19];
    const float* lbb  = (const float*)d_in[20];
    const float* W1   = (const float*)d_in[21];
    const float* b1   = (const float*)d_in[22];
    const float* W2   = (const float*)d_in[23];
    const float* b2   = (const float*)d_in[24];
    const float* om   = (const float*)d_in[25];
    const float* hw   = (const float*)d_in[26];
    const float* hb   = (const float*)d_in[27];
    float* out = (float*)d_out;

    float *xc, *q, *k, *v, *Qp, *Kp, *KV, *Ks, *at, *tp, *h1, *pl, *im;
    cudaGetSymbolAddress((void**)&xc, g_xc);
    cudaGetSymbolAddress((void**)&q,  g_q);
    cudaGetSymbolAddress((void**)&k,  g_k);
    cudaGetSymbolAddress((void**)&v,  g_v);
    cudaGetSymbolAddress((void**)&Qp, g_Qp);
    cudaGetSymbolAddress((void**)&Kp, g_Kp);
    cudaGetSymbolAddress((void**)&KV, g_KV);
    cudaGetSymbolAddress((void**)&Ks, g_Ks);
    cudaGetSymbolAddress((void**)&at, g_at);
    cudaGetSymbolAddress((void**)&tp, g_tp);
    cudaGetSymbolAddress((void**)&h1, g_h1);
    cudaGetSymbolAddress((void**)&pl, g_pl);
    cudaGetSymbolAddress((void**)&im, g_im);

    // ---- patch embedding: im2col + GEMM + LN + pos, cls token ----
    {
        int tot = NP_ * 768;
        im2col_kernel<<<(tot + 255) / 256, 256>>>(x, im);
        tgemm_kernel<<<dim3(3, NP_ / 128), 256>>>(im, pw, pb, nullptr, q, 768, D_, NP_, 0);
        ln_patch_kernel<<<NP_, 192>>>(q, peg, peb, pos, xc);
        cls_kernel<<<B_, 192>>>(cls, pos, xc);
    }

    const dim3 gD(3, NTP_ / 128);    // Mo=192
    const dim3 gF(12, NTP_ / 128);   // Mo=768

    for (int i = 0; i < 12; i++) {
        const float* om_i = om + (size_t)i * DH_ * MM_;
        tgemm_kernel<<<gD, 256>>>(xc, Wq + (size_t)i * D_ * D_, bq + i * D_, nullptr, q, D_, D_, NTP_, 0);
        tgemm_kernel<<<gD, 256>>>(xc, Wk + (size_t)i * D_ * D_, bk + i * D_, nullptr, k, D_, D_, NTP_, 0);
        tgemm_kernel<<<gD, 256>>>(xc, Wv + (size_t)i * D_ * D_, bv + i * D_, nullptr, v, D_, D_, NTP_, 0);
        favor_kernel<<<dim3(NT_, H_), 128>>>(q, om_i, Qp);
        favor_kernel<<<dim3(NT_, H_), 128>>>(k, om_i, Kp);
        kv_kernel<<<dim3(B_, H_), 256>>>(Kp, v, KV, Ks);
        attn_kernel<<<NT_, 192>>>(Qp, KV, Ks, at);
        // xc_new_pre = xc + attn @ Wo^T + bo
        tgemm_kernel<<<gD, 256>>>(at, Wo + (size_t)i * D_ * D_, bo + i * D_, xc, tp, D_, D_, NTP_, 0);
        ln_kernel<<<NT_, 192>>>(tp, l1g + i * D_, l1b + i * D_, xc);
        // MLP
        tgemm_kernel<<<gF, 256>>>(xc, W1 + (size_t)i * FF_ * D_, b1 + i * FF_, nullptr, h1, D_, FF_, NTP_, 1);
        tgemm_kernel<<<gD, 256>>>(h1, W2 + (size_t)i * D_ * FF_, b2 + i * D_, xc, tp, FF_, D_, NTP_, 0);
        dln_kernel<<<NT_, 192>>>(tp, l2g + i * D_, l2b + i * D_, lbg + i * D_, lbb + i * D_, xc);

        if (i == 3 || i == 7 || i == 11) {
            int j = (i == 3) ? 0 : (i == 7) ? 1 : 2;
            pool_kernel<<<B_, 192>>>(xc, pl);
            tgemm_kernel<<<dim3(16, 1), 256>>>(pl, hw + (size_t)j * NCLS_ * D_, hb + j * NCLS_,
                                               nullptr, out + (size_t)j * B_ * NCLS_, D_, NCLS_, B_, 0);
        }
    }
}

// round 7
// speedup vs baseline: 2.4344x; 1.4989x over previous
#include <cuda_runtime.h>
#include <math.h>
#include <stdint.h>

#define B_    64
#define L_    197
#define D_    192
#define H_    3
#define DH_   64
#define MM_   128
#define TM_   256           // 2M
#define NT_   (B_*L_)       // 12608
#define NTP_  12672         // 99 * 128 (padded rows)
#define FF_   768
#define NCLS_ 1000
#define NP_   (B_*196)      // 12544

// ---------------- scratch (static device globals; zero-initialized) ----------------
__device__ float g_xc [NTP_*D_];
__device__ float g_q  [NTP_*D_];
__device__ float g_k  [NTP_*D_];
__device__ float g_v  [NTP_*D_];
__device__ float g_Qp [NT_*H_*TM_];
__device__ float g_Kp [NT_*H_*TM_];
__device__ float g_KVt[B_*H_*DH_*TM_];   // [bh][d][m] transposed
__device__ float g_Ks [B_*H_*TM_];
__device__ float g_at [NTP_*D_];
__device__ float g_tp [NTP_*D_];
__device__ float g_h1 [NTP_*FF_];
__device__ float g_pl [128*D_];
__device__ float g_im [NP_*768];
__device__ float g_omT[MM_*DH_];         // transposed, pre-scaled omega
__device__ float g_ofq[NT_*H_];
__device__ float g_ofk[NT_*H_];
__device__ float g_Z  [NT_*H_];

__device__ __forceinline__ uint32_t f2tf(float f) {
    uint32_t o; asm("cvt.rna.tf32.f32 %0, %1;" : "=r"(o) : "f"(f)); return o;
}

#define MMA_TF32(acc, af, bf)                                               \
    asm volatile(                                                           \
        "mma.sync.aligned.m16n8k8.row.col.f32.tf32.tf32.f32 "               \
        "{%0,%1,%2,%3}, {%4,%5,%6,%7}, {%8,%9}, {%0,%1,%2,%3};\n"           \
        : "+f"(acc[0]), "+f"(acc[1]), "+f"(acc[2]), "+f"(acc[3])            \
        : "r"(af[0]), "r"(af[1]), "r"(af[2]), "r"(af[3]),                   \
          "r"(bf[0]), "r"(bf[1]))

// ---------------- TF32 tensor-core GEMM (dense layers) ----------------
// C[N,Mo] = A[N,K] @ W[Mo,K]^T (+bias, +add, +relu). Block tile 128x64, BK=32.
__global__ __launch_bounds__(256) void tgemm_kernel(
    const float* __restrict__ A, const float* __restrict__ W,
    const float* __restrict__ bias, const float* __restrict__ add,
    float* __restrict__ C, int K, int Mo, int Nstore, int relu)
{
    __shared__ __align__(16) uint32_t As[128*36];
    __shared__ __align__(16) uint32_t Ws[64*36];
    const int bm = blockIdx.y * 128;
    const int bn = blockIdx.x * 64;
    const int tid  = threadIdx.x;
    const int lane = tid & 31, wid = tid >> 5;
    const int warp_m = wid >> 1, warp_n = wid & 1;
    const int gid = lane >> 2, tg = lane & 3;

    float acc[2][4][4];
#pragma unroll
    for (int a = 0; a < 2; a++)
#pragma unroll
        for (int b = 0; b < 4; b++)
#pragma unroll
            for (int c = 0; c < 4; c++) acc[a][b][c] = 0.f;

    const int niter = K >> 5;
    float4 pa[4], pw[2];

#pragma unroll
    for (int p = 0; p < 4; p++) {
        int idx = tid + p * 256;
        int r = idx >> 3, c = (idx & 7) << 2;
        pa[p] = *reinterpret_cast<const float4*>(A + (size_t)(bm + r) * K + c);
    }
#pragma unroll
    for (int p = 0; p < 2; p++) {
        int idx = tid + p * 256;
        int r = idx >> 3, c = (idx & 7) << 2;
        int wr = bn + r;
        pw[p] = (wr < Mo) ? *reinterpret_cast<const float4*>(W + (size_t)wr * K + c)
                          : make_float4(0.f, 0.f, 0.f, 0.f);
    }

    for (int it = 0; it < niter; it++) {
#pragma unroll
        for (int p = 0; p < 4; p++) {
            int idx = tid + p * 256;
            int r = idx >> 3, c = (idx & 7) << 2;
            uint32_t* d = &As[r * 36 + c];
            d[0] = f2tf(pa[p].x); d[1] = f2tf(pa[p].y);
            d[2] = f2tf(pa[p].z); d[3] = f2tf(pa[p].w);
        }
#pragma unroll
        for (int p = 0; p < 2; p++) {
            int idx = tid + p * 256;
            int r = idx >> 3, c = (idx & 7) << 2;
            uint32_t* d = &Ws[r * 36 + c];
            d[0] = f2tf(pw[p].x); d[1] = f2tf(pw[p].y);
            d[2] = f2tf(pw[p].z); d[3] = f2tf(pw[p].w);
        }
        __syncthreads();

        if (it + 1 < niter) {
            int k0 = (it + 1) << 5;
#pragma unroll
            for (int p = 0; p < 4; p++) {
                int idx = tid + p * 256;
                int r = idx >> 3, c = (idx & 7) << 2;
                pa[p] = *reinterpret_cast<const float4*>(A + (size_t)(bm + r) * K + k0 + c);
            }
#pragma unroll
            for (int p = 0; p < 2; p++) {
                int idx = tid + p * 256;
                int r = idx >> 3, c = (idx & 7) << 2;
                int wr = bn + r;
                pw[p] = (wr < Mo) ? *reinterpret_cast<const float4*>(W + (size_t)wr * K + k0 + c)
                                  : make_float4(0.f, 0.f, 0.f, 0.f);
            }
        }

#pragma unroll
        for (int ks = 0; ks < 4; ks++) {
            const int kb = ks * 8;
            uint32_t af[2][4], bf[4][2];
#pragma unroll
            for (int fm = 0; fm < 2; fm++) {
                int r0 = warp_m * 32 + fm * 16 + gid;
                af[fm][0] = As[r0 * 36 + kb + tg];
                af[fm][1] = As[(r0 + 8) * 36 + kb + tg];
                af[fm][2] = As[r0 * 36 + kb + tg + 4];
                af[fm][3] = As[(r0 + 8) * 36 + kb + tg + 4];
            }
#pragma unroll
            for (int fn = 0; fn < 4; fn++) {
                int n = warp_n * 32 + fn * 8 + gid;
                bf[fn][0] = Ws[n * 36 + kb + tg];
                bf[fn][1] = Ws[n * 36 + kb + tg + 4];
            }
#pragma unroll
            for (int fm = 0; fm < 2; fm++)
#pragma unroll
                for (int fn = 0; fn < 4; fn++) MMA_TF32(acc[fm][fn], af[fm], bf[fn]);
        }
        __syncthreads();
    }

#pragma unroll
    for (int fm = 0; fm < 2; fm++) {
        int rbase = bm + warp_m * 32 + fm * 16 + gid;
#pragma unroll
        for (int fn = 0; fn < 4; fn++) {
            int c = bn + warp_n * 32 + fn * 8 + (tg << 1);
            if (c < Mo) {
                float bc0 = bias[c], bc1 = bias[c + 1];
#pragma unroll
                for (int h = 0; h < 2; h++) {
                    int row = rbase + h * 8;
                    if (row < Nstore) {
                        float v0 = acc[fm][fn][h * 2 + 0] + bc0;
                        float v1 = acc[fm][fn][h * 2 + 1] + bc1;
                        if (add) {
                            float2 ad = *reinterpret_cast<const float2*>(add + (size_t)row * Mo + c);
                            v0 += ad.x; v1 += ad.y;
                        }
                        if (relu) { v0 = fmaxf(v0, 0.f); v1 = fmaxf(v1, 0.f); }
                        *reinterpret_cast<float2*>(C + (size_t)row * Mo + c) = make_float2(v0, v1);
                    }
                }
            }
        }
    }
}

// ---------------- FAVOR feature-map GEMM ----------------
// grid (2, NTP/128, 6): z%3 = head, z/3 selects (q->Qp) or (k->Kp).
// u = Xs @ omT^T  (Xs rows stride 192, K=64), epilogue exp(+-u - off) * 1/16.
__global__ __launch_bounds__(256) void favor_gemm_kernel(
    const float* __restrict__ Qin, const float* __restrict__ Kin,
    const float* __restrict__ omT,
    const float* __restrict__ OFFq, const float* __restrict__ OFFk,
    float* __restrict__ QPhi, float* __restrict__ KPhi)
{
    __shared__ __align__(16) uint32_t As[128*36];
    __shared__ __align__(16) uint32_t Ws[64*36];
    const int hh  = blockIdx.z % 3;
    const int sel = blockIdx.z / 3;
    const float* A   = (sel ? Kin : Qin) + hh * DH_;
    const float* OFF = sel ? OFFk : OFFq;
    float* Phi       = sel ? KPhi : QPhi;

    const int bm = blockIdx.y * 128;
    const int bn = blockIdx.x * 64;
    const int tid  = threadIdx.x;
    const int lane = tid & 31, wid = tid >> 5;
    const int warp_m = wid >> 1, warp_n = wid & 1;
    const int gid = lane >> 2, tg = lane & 3;

    float acc[2][4][4];
#pragma unroll
    for (int a = 0; a < 2; a++)
#pragma unroll
        for (int b = 0; b < 4; b++)
#pragma unroll
            for (int c = 0; c < 4; c++) acc[a][b][c] = 0.f;

    for (int it = 0; it < 2; it++) {
        const int k0 = it << 5;
#pragma unroll
        for (int p = 0; p < 4; p++) {
            int idx = tid + p * 256;
            int r = idx >> 3, c = (idx & 7) << 2;
            float4 v = *reinterpret_cast<const float4*>(A + (size_t)(bm + r) * D_ + k0 + c);
            uint32_t* d = &As[r * 36 + c];
            d[0] = f2tf(v.x); d[1] = f2tf(v.y); d[2] = f2tf(v.z); d[3] = f2tf(v.w);
        }
#pragma unroll
        for (int p = 0; p < 2; p++) {
            int idx = tid + p * 256;
            int r = idx >> 3, c = (idx & 7) << 2;
            float4 v = *reinterpret_cast<const float4*>(omT + (size_t)(bn + r) * DH_ + k0 + c);
            uint32_t* d = &Ws[r * 36 + c];
            d[0] = f2tf(v.x); d[1] = f2tf(v.y); d[2] = f2tf(v.z); d[3] = f2tf(v.w);
        }
        __syncthreads();
#pragma unroll
        for (int ks = 0; ks < 4; ks++) {
            const int kb = ks * 8;
            uint32_t af[2][4], bf[4][2];
#pragma unroll
            for (int fm = 0; fm < 2; fm++) {
                int r0 = warp_m * 32 + fm * 16 + gid;
                af[fm][0] = As[r0 * 36 + kb + tg];
                af[fm][1] = As[(r0 + 8) * 36 + kb + tg];
                af[fm][2] = As[r0 * 36 + kb + tg + 4];
                af[fm][3] = As[(r0 + 8) * 36 + kb + tg + 4];
            }
#pragma unroll
            for (int fn = 0; fn < 4; fn++) {
                int n = warp_n * 32 + fn * 8 + gid;
                bf[fn][0] = Ws[n * 36 + kb + tg];
                bf[fn][1] = Ws[n * 36 + kb + tg + 4];
            }
#pragma unroll
            for (int fm = 0; fm < 2; fm++)
#pragma unroll
                for (int fn = 0; fn < 4; fn++) MMA_TF32(acc[fm][fn], af[fm], bf[fn]);
        }
        __syncthreads();
    }

    // epilogue: Phi[t*768 + h*256 + m] = exp(u - off)/16 ; [+128+m] = exp(-u - off)/16
#pragma unroll
    for (int fm = 0; fm < 2; fm++) {
        int rbase = bm + warp_m * 32 + fm * 16 + gid;
#pragma unroll
        for (int fn = 0; fn < 4; fn++) {
            int m = bn + warp_n * 32 + fn * 8 + (tg << 1);
#pragma unroll
            for (int h = 0; h < 2; h++) {
                int t = rbase + h * 8;
                if (t < NT_) {
                    float off = OFF[t * 3 + hh];
                    float u0 = acc[fm][fn][h * 2 + 0];
                    float u1 = acc[fm][fn][h * 2 + 1];
                    float2 e1 = make_float2(expf(u0 - off) * 0.0625f, expf(u1 - off) * 0.0625f);
                    float2 e2 = make_float2(expf(-u0 - off) * 0.0625f, expf(-u1 - off) * 0.0625f);
                    size_t base = (size_t)t * 768 + hh * 256 + m;
                    *reinterpret_cast<float2*>(Phi + base)       = e1;
                    *reinterpret_cast<float2*>(Phi + base + 128) = e2;
                }
            }
        }
    }
}

// ---------------- attention apply GEMM: at[t, h*64+d] = Z * (Qp @ KVt^T) --------
// grid (2, B*H): per (b,h) GEMM M=197, N=64, K=256.
__global__ __launch_bounds__(256) void attn_gemm_kernel(
    const float* __restrict__ Qp, const float* __restrict__ KVt,
    const float* __restrict__ Z, float* __restrict__ O)
{
    __shared__ __align__(16) uint32_t As[128*36];
    __shared__ __align__(16) uint32_t Ws[64*36];
    const int bh = blockIdx.y;
    const int b = bh / 3, hh = bh % 3;
    const float* A = Qp + (size_t)b * L_ * 768 + hh * 256;
    const float* W = KVt + (size_t)bh * DH_ * TM_;

    const int bm = blockIdx.x * 128;
    const int tid  = threadIdx.x;
    const int lane = tid & 31, wid = tid >> 5;
    const int warp_m = wid >> 1, warp_n = wid & 1;
    const int gid = lane >> 2, tg = lane & 3;

    float acc[2][4][4];
#pragma unroll
    for (int a = 0; a < 2; a++)
#pragma unroll
        for (int c2 = 0; c2 < 4; c2++)
#pragma unroll
            for (int c = 0; c < 4; c++) acc[a][c2][c] = 0.f;

    for (int it = 0; it < 8; it++) {
        const int k0 = it << 5;
#pragma unroll
        for (int p = 0; p < 4; p++) {
            int idx = tid + p * 256;
            int r = idx >> 3, c = (idx & 7) << 2;
            int lr = bm + r;
            float4 v = (lr < L_) ? *reinterpret_cast<const float4*>(A + (size_t)lr * 768 + k0 + c)
                                 : make_float4(0.f, 0.f, 0.f, 0.f);
            uint32_t* d = &As[r * 36 + c];
            d[0] = f2tf(v.x); d[1] = f2tf(v.y); d[2] = f2tf(v.z); d[3] = f2tf(v.w);
        }
#pragma unroll
        for (int p = 0; p < 2; p++) {
            int idx = tid + p * 256;
            int r = idx >> 3, c = (idx & 7) << 2;
            float4 v = *reinterpret_cast<const float4*>(W + (size_t)r * TM_ + k0 + c);
            uint32_t* d = &Ws[r * 36 + c];
            d[0] = f2tf(v.x); d[1] = f2tf(v.y); d[2] = f2tf(v.z); d[3] = f2tf(v.w);
        }
        __syncthreads();
#pragma unroll
        for (int ks = 0; ks < 4; ks++) {
            const int kb = ks * 8;
            uint32_t af[2][4], bf[4][2];
#pragma unroll
            for (int fm = 0; fm < 2; fm++) {
                int r0 = warp_m * 32 + fm * 16 + gid;
                af[fm][0] = As[r0 * 36 + kb + tg];
                af[fm][1] = As[(r0 + 8) * 36 + kb + tg];
                af[fm][2] = As[r0 * 36 + kb + tg + 4];
                af[fm][3] = As[(r0 + 8) * 36 + kb + tg + 4];
            }
#pragma unroll
            for (int fn = 0; fn < 4; fn++) {
                int n = warp_n * 32 + fn * 8 + gid;
                bf[fn][0] = Ws[n * 36 + kb + tg];
                bf[fn][1] = Ws[n * 36 + kb + tg + 4];
            }
#pragma unroll
            for (int fm = 0; fm < 2; fm++)
#pragma unroll
                for (int fn = 0; fn < 4; fn++) MMA_TF32(acc[fm][fn], af[fm], bf[fn]);
        }
        __syncthreads();
    }

#pragma unroll
    for (int fm = 0; fm < 2; fm++) {
        int rbase = bm + warp_m * 32 + fm * 16 + gid;
#pragma unroll
        for (int fn = 0; fn < 4; fn++) {
            int c = warp_n * 32 + fn * 8 + (tg << 1);
#pragma unroll
            for (int h = 0; h < 2; h++) {
                int lr = rbase + h * 8;
                if (lr < L_) {
                    int t = b * L_ + lr;
                    float z = Z[t * 3 + hh];
                    float v0 = acc[fm][fn][h * 2 + 0] * z;
                    float v1 = acc[fm][fn][h * 2 + 1] * z;
                    *reinterpret_cast<float2*>(O + (size_t)t * D_ + hh * 64 + c) = make_float2(v0, v1);
                }
            }
        }
    }
}

// ---------------- omega transpose + scale ----------------
__global__ void omt_kernel(const float* __restrict__ om, float* __restrict__ omT)
{
    int i = blockIdx.x * 256 + threadIdx.x;   // 8192
    int m = i >> 6, d = i & 63;
    omT[i] = om[d * MM_ + m] * 0.35355339059327373f;
}

// ---------------- per-(t,h) offsets: 0.5*temp*|x|^2 for q and k ----------------
__global__ void offs_kernel(const float* __restrict__ q, const float* __restrict__ k,
                            float* __restrict__ oq, float* __restrict__ ok)
{
    int w = (blockIdx.x * 256 + threadIdx.x) >> 5;
    int lane = threadIdx.x & 31;
    if (w >= NT_ * 3) return;
    int t = w / 3, h = w % 3;
    const float* a = q + (size_t)t * D_ + h * 64;
    const float* b = k + (size_t)t * D_ + h * 64;
    float s1 = 0.f, s2 = 0.f;
#pragma unroll
    for (int j = 0; j < 2; j++) {
        float x = a[lane + j * 32]; s1 += x * x;
        float y = b[lane + j * 32]; s2 += y * y;
    }
#pragma unroll
    for (int o = 16; o; o >>= 1) {
        s1 += __shfl_down_sync(0xffffffffu, s1, o);
        s2 += __shfl_down_sync(0xffffffffu, s2, o);
    }
    if (!lane) { oq[w] = 0.0625f * s1; ok[w] = 0.0625f * s2; }  // 0.5*temp = 0.5*0.125
}

// ---------------- Z = 1/(Qp . Ksum + eps) ----------------
__global__ void z_kernel(const float* __restrict__ Qp, const float* __restrict__ Ks,
                         float* __restrict__ Z)
{
    int w = (blockIdx.x * 256 + threadIdx.x) >> 5;
    int lane = threadIdx.x & 31;
    if (w >= NT_ * 3) return;
    int t = w / 3, h = w % 3;
    int b = t / L_;
    const float* qp = Qp + (size_t)t * 768 + h * 256;
    const float* ks = Ks + (size_t)(b * 3 + h) * 256;
    float s = 0.f;
#pragma unroll
    for (int j = 0; j < 8; j++) { int i = lane + j * 32; s += qp[i] * ks[i]; }
#pragma unroll
    for (int o = 16; o; o >>= 1) s += __shfl_down_sync(0xffffffffu, s, o);
    if (!lane) Z[w] = 1.f / (s + 1e-6f);
}

// ---------------- KVt = (Kp^T @ V) transposed, plus Ksum ----------------
__global__ void kv_kernel(const float* __restrict__ Kp, const float* __restrict__ V,
                          float* __restrict__ KVt, float* __restrict__ Ks)
{
    int b = blockIdx.x, h = blockIdx.y, m = threadIdx.x;  // 256 threads
    __shared__ float vs[64];
    float acc[64];
#pragma unroll
    for (int d = 0; d < 64; d++) acc[d] = 0.f;
    float ks = 0.f;
    for (int l = 0; l < L_; l++) {
        int t = b * L_ + l;
        if (m < 64) vs[m] = V[(size_t)t * D_ + h * DH_ + m];
        __syncthreads();
        float kp = Kp[(size_t)t * 768 + h * 256 + m];
        ks += kp;
#pragma unroll
        for (int d = 0; d < 64; d++) acc[d] += kp * vs[d];
        __syncthreads();
    }
    size_t base = (size_t)(b * H_ + h) * DH_ * TM_;
#pragma unroll
    for (int d = 0; d < 64; d++) KVt[base + (size_t)d * TM_ + m] = acc[d];
    Ks[(size_t)(b * H_ + h) * TM_ + m] = ks;
}

// ---------------- im2col for 16x16/stride16 conv ----------------
__global__ void im2col_kernel(const float* __restrict__ x, float* __restrict__ out)
{
    int o = blockIdx.x * 256 + threadIdx.x;
    if (o >= NP_ * 768) return;
    int kk = o % 768;
    int t  = o / 768;
    int b = t / 196, p = t % 196;
    int gh = p / 14, gw = p % 14;
    int c = kk / 256, r = kk % 256;
    int pp = r / 16, qq = r % 16;
    out[o] = x[((size_t)(b * 3 + c) * 224 + gh * 16 + pp) * 224 + gw * 16 + qq];
}

// ---------------- LayerNorm helpers (192 threads/block) ----------------
__device__ __forceinline__ void block_stats192(float x, float* sh, float& mu, float& rs)
{
    float s = x, ss = x * x;
#pragma unroll
    for (int o = 16; o; o >>= 1) {
        s  += __shfl_down_sync(0xffffffffu, s,  o);
        ss += __shfl_down_sync(0xffffffffu, ss, o);
    }
    int w = threadIdx.x >> 5;
    if ((threadIdx.x & 31) == 0) { sh[w] = s; sh[6 + w] = ss; }
    __syncthreads();
    if (threadIdx.x == 0) {
        float a = 0.f, b = 0.f;
        for (int i = 0; i < 6; i++) { a += sh[i]; b += sh[6 + i]; }
        float m = a * (1.f / 192.f);
        float v = b * (1.f / 192.f) - m * m;
        sh[0] = m; sh[1] = rsqrtf(v + 1e-5f);
    }
    __syncthreads();
    mu = sh[0]; rs = sh[1];
}

__global__ void ln_kernel(const float* __restrict__ X, const float* __restrict__ g,
                          const float* __restrict__ bb, float* __restrict__ Y)
{
    int row = blockIdx.x, tid = threadIdx.x;
    __shared__ float sh[12];
    float x = X[(size_t)row * D_ + tid];
    float mu, rs;
    block_stats192(x, sh, mu, rs);
    Y[(size_t)row * D_ + tid] = (x - mu) * rs * g[tid] + bb[tid];
}

__global__ void dln_kernel(const float* __restrict__ X,
                           const float* __restrict__ g1, const float* __restrict__ b1,
                           const float* __restrict__ g2, const float* __restrict__ b2,
                           float* __restrict__ Y)
{
    int row = blockIdx.x, tid = threadIdx.x;
    __shared__ float sh[12];
    float x = X[(size_t)row * D_ + tid];
    float mu, rs;
    block_stats192(x, sh, mu, rs);
    float y = (x - mu) * rs * g1[tid] + b1[tid];
    __syncthreads();
    block_stats192(y, sh, mu, rs);
    Y[(size_t)row * D_ + tid] = (y - mu) * rs * g2[tid] + b2[tid];
}

__global__ void ln_patch_kernel(const float* __restrict__ T, const float* __restrict__ g,
                                const float* __restrict__ bb, const float* __restrict__ pos,
                                float* __restrict__ XC)
{
    int row = blockIdx.x, tid = threadIdx.x;   // row in [0, NP_)
    __shared__ float sh[12];
    float x = T[(size_t)row * D_ + tid];
    float mu, rs;
    block_stats192(x, sh, mu, rs);
    int b = row / 196, p = row % 196;
    float v = (x - mu) * rs * g[tid] + bb[tid] + pos[(size_t)(1 + p) * D_ + tid];
    XC[((size_t)b * L_ + 1 + p) * D_ + tid] = v;
}

__global__ void cls_kernel(const float* __restrict__ cls, const float* __restrict__ pos,
                           float* __restrict__ XC)
{
    int b = blockIdx.x, tid = threadIdx.x;
    XC[(size_t)b * L_ * D_ + tid] = cls[tid] + pos[tid];
}

// ---------------- mean pool over sequence ----------------
__global__ void pool_kernel(const float* __restrict__ XC, float* __restrict__ P)
{
    int b = blockIdx.x, tid = threadIdx.x;
    float s = 0.f;
    for (int l = 0; l < L_; l++) s += XC[((size_t)b * L_ + l) * D_ + tid];
    P[(size_t)b * D_ + tid] = s * (1.f / 197.f);
}

// ---------------- launcher ----------------
extern "C" void kernel_launch(void* const* d_in, const int* in_sizes, int n_in,
                              void* d_out, int out_size)
{
    (void)in_sizes; (void)n_in; (void)out_size;
    const float* x    = (const float*)d_in[0];
    const float* pw   = (const float*)d_in[1];
    const float* pb   = (const float*)d_in[2];
    const float* peg  = (const float*)d_in[3];
    const float* peb  = (const float*)d_in[4];
    const float* cls  = (const float*)d_in[5];
    const float* pos  = (const float*)d_in[6];
    const float* Wq   = (const float*)d_in[7];
    const float* bq   = (const float*)d_in[8];
    const float* Wk   = (const float*)d_in[9];
    const float* bk   = (const float*)d_in[10];
    const float* Wv   = (const float*)d_in[11];
    const float* bv   = (const float*)d_in[12];
    const float* Wo   = (const float*)d_in[13];
    const float* bo   = (const float*)d_in[14];
    const float* l1g  = (const float*)d_in[15];
    const float* l1b  = (const float*)d_in[16];
    const float* l2g  = (const float*)d_in[17];
    const float* l2b  = (const float*)d_in[18];
    const float* lbg  = (const float*)d_in[19];
    const float* lbb  = (const float*)d_in[20];
    const float* W1   = (const float*)d_in[21];
    const float* b1   = (const float*)d_in[22];
    const float* W2   = (const float*)d_in[23];
    const float* b2   = (const float*)d_in[24];
    const float* om   = (const float*)d_in[25];
    const float* hw   = (const float*)d_in[26];
    const float* hb   = (const float*)d_in[27];
    float* out = (float*)d_out;

    float *xc, *q, *k, *v, *Qp, *Kp, *KVt, *Ks, *at, *tp, *h1, *pl, *im;
    float *omT, *ofq, *ofk, *Z;
    cudaGetSymbolAddress((void**)&xc,  g_xc);
    cudaGetSymbolAddress((void**)&q,   g_q);
    cudaGetSymbolAddress((void**)&k,   g_k);
    cudaGetSymbolAddress((void**)&v,   g_v);
    cudaGetSymbolAddress((void**)&Qp,  g_Qp);
    cudaGetSymbolAddress((void**)&Kp,  g_Kp);
    cudaGetSymbolAddress((void**)&KVt, g_KVt);
    cudaGetSymbolAddress((void**)&Ks,  g_Ks);
    cudaGetSymbolAddress((void**)&at,  g_at);
    cudaGetSymbolAddress((void**)&tp,  g_tp);
    cudaGetSymbolAddress((void**)&h1,  g_h1);
    cudaGetSymbolAddress((void**)&pl,  g_pl);
    cudaGetSymbolAddress((void**)&im,  g_im);
    cudaGetSymbolAddress((void**)&omT, g_omT);
    cudaGetSymbolAddress((void**)&ofq, g_ofq);
    cudaGetSymbolAddress((void**)&ofk, g_ofk);
    cudaGetSymbolAddress((void**)&Z,   g_Z);

    // ---- patch embedding: im2col + GEMM + LN + pos, cls token ----
    {
        int tot = NP_ * 768;
        im2col_kernel<<<(tot + 255) / 256, 256>>>(x, im);
        tgemm_kernel<<<dim3(3, NP_ / 128), 256>>>(im, pw, pb, nullptr, q, 768, D_, NP_, 0);
        ln_patch_kernel<<<NP_, 192>>>(q, peg, peb, pos, xc);
        cls_kernel<<<B_, 192>>>(cls, pos, xc);
    }

    const dim3 gD(3, NTP_ / 128);    // Mo=192
    const dim3 gF(12, NTP_ / 128);   // Mo=768
    const int gw = (NT_ * 3 * 32 + 255) / 256;   // warp-per-(t,h) grids

    for (int i = 0; i < 12; i++) {
        tgemm_kernel<<<gD, 256>>>(xc, Wq + (size_t)i * D_ * D_, bq + i * D_, nullptr, q, D_, D_, NTP_, 0);
        tgemm_kernel<<<gD, 256>>>(xc, Wk + (size_t)i * D_ * D_, bk + i * D_, nullptr, k, D_, D_, NTP_, 0);
        tgemm_kernel<<<gD, 256>>>(xc, Wv + (size_t)i * D_ * D_, bv + i * D_, nullptr, v, D_, D_, NTP_, 0);
        omt_kernel<<<32, 256>>>(om + (size_t)i * DH_ * MM_, omT);
        offs_kernel<<<gw, 256>>>(q, k, ofq, ofk);
        favor_gemm_kernel<<<dim3(2, NTP_ / 128, 6), 256>>>(q, k, omT, ofq, ofk, Qp, Kp);
        kv_kernel<<<dim3(B_, H_), 256>>>(Kp, v, KVt, Ks);
        z_kernel<<<gw, 256>>>(Qp, Ks, Z);
        attn_gemm_kernel<<<dim3(2, B_ * H_), 256>>>(Qp, KVt, Z, at);
        // xc_new_pre = xc + attn @ Wo^T + bo
        tgemm_kernel<<<gD, 256>>>(at, Wo + (size_t)i * D_ * D_, bo + i * D_, xc, tp, D_, D_, NTP_, 0);
        ln_kernel<<<NT_, 192>>>(tp, l1g + i * D_, l1b + i * D_, xc);
        // MLP
        tgemm_kernel<<<gF, 256>>>(xc, W1 + (size_t)i * FF_ * D_, b1 + i * FF_, nullptr, h1, D_, FF_, NTP_, 1);
        tgemm_kernel<<<gD, 256>>>(h1, W2 + (size_t)i * D_ * FF_, b2 + i * D_, xc, tp, FF_, D_, NTP_, 0);
        dln_kernel<<<NT_, 192>>>(tp, l2g + i * D_, l2b + i * D_, lbg + i * D_, lbb + i * D_, xc);

        if (i == 3 || i == 7 || i == 11) {
            int j = (i == 3) ? 0 : (i == 7) ? 1 : 2;
            pool_kernel<<<B_, 192>>>(xc, pl);
            tgemm_kernel<<<dim3(16, 1), 256>>>(pl, hw + (size_t)j * NCLS_ * D_, hb + j * NCLS_,
                                               nullptr, out + (size_t)j * B_ * NCLS_, D_, NCLS_, B_, 0);
        }
    }
}

// round 8
// speedup vs baseline: 2.5725x; 1.0567x over previous
#include <cuda_runtime.h>
#include <math.h>
#include <stdint.h>

#define B_    64
#define L_    197
#define D_    192
#define H_    3
#define DH_   64
#define MM_   128
#define TM_   256           // 2M
#define NT_   (B_*L_)       // 12608
#define NTP_  12672         // 99 * 128 (padded rows)
#define FF_   768
#define NCLS_ 1000
#define NP_   (B_*196)      // 12544

// ---------------- scratch (static device globals; zero-initialized) ----------------
__device__ float g_xc [NTP_*D_];
__device__ float g_q  [NTP_*D_];
__device__ float g_k  [NTP_*D_];
__device__ float g_v  [NTP_*D_];
__device__ float g_Qp [NT_*H_*TM_];
__device__ float g_Kp [NT_*H_*TM_];
__device__ float g_KVt[B_*H_*DH_*TM_];   // [bh][d][m] transposed
__device__ float g_Ks [B_*H_*TM_];
__device__ float g_at [NTP_*D_];
__device__ float g_tp [NTP_*D_];
__device__ float g_h1 [NTP_*FF_];
__device__ float g_pl [128*D_];
__device__ float g_im [NP_*768];
__device__ float g_omT[12*MM_*DH_];      // per-layer transposed, pre-scaled omega

__device__ __forceinline__ uint32_t f2tf(float f) {
    uint32_t o; asm("cvt.rna.tf32.f32 %0, %1;" : "=r"(o) : "f"(f)); return o;
}

#define MMA_TF32(acc, af, bf)                                               \
    asm volatile(                                                           \
        "mma.sync.aligned.m16n8k8.row.col.f32.tf32.tf32.f32 "               \
        "{%0,%1,%2,%3}, {%4,%5,%6,%7}, {%8,%9}, {%0,%1,%2,%3};\n"           \
        : "+f"(acc[0]), "+f"(acc[1]), "+f"(acc[2]), "+f"(acc[3])            \
        : "r"(af[0]), "r"(af[1]), "r"(af[2]), "r"(af[3]),                   \
          "r"(bf[0]), "r"(bf[1]))

// fragment loads from smem (pitch 36, conflict-free)
#define LOAD_FRAGS(As, Ws, kb)                                              \
    uint32_t af[2][4], bf[4][2];                                            \
    _Pragma("unroll")                                                       \
    for (int fm = 0; fm < 2; fm++) {                                        \
        int r0 = warp_m * 32 + fm * 16 + gid;                               \
        af[fm][0] = As[r0 * 36 + kb + tg];                                  \
        af[fm][1] = As[(r0 + 8) * 36 + kb + tg];                            \
        af[fm][2] = As[r0 * 36 + kb + tg + 4];                              \
        af[fm][3] = As[(r0 + 8) * 36 + kb + tg + 4];                        \
    }                                                                       \
    _Pragma("unroll")                                                       \
    for (int fn = 0; fn < 4; fn++) {                                        \
        int n = warp_n * 32 + fn * 8 + gid;                                 \
        bf[fn][0] = Ws[n * 36 + kb + tg];                                   \
        bf[fn][1] = Ws[n * 36 + kb + tg + 4];                               \
    }

// ---------------- TF32 tensor-core GEMM (generic) ----------------
// C[N,Mo] = A[N,K] @ W[Mo,K]^T (+bias, +add, +relu). Block tile 128x64, BK=32.
__global__ __launch_bounds__(256) void tgemm_kernel(
    const float* __restrict__ A, const float* __restrict__ W,
    const float* __restrict__ bias, const float* __restrict__ add,
    float* __restrict__ C, int K, int Mo, int Nstore, int relu)
{
    __shared__ __align__(16) uint32_t As[128*36];
    __shared__ __align__(16) uint32_t Ws[64*36];
    const int bm = blockIdx.y * 128;
    const int bn = blockIdx.x * 64;
    const int tid  = threadIdx.x;
    const int lane = tid & 31, wid = tid >> 5;
    const int warp_m = wid >> 1, warp_n = wid & 1;
    const int gid = lane >> 2, tg = lane & 3;

    float acc[2][4][4];
#pragma unroll
    for (int a = 0; a < 2; a++)
#pragma unroll
        for (int b = 0; b < 4; b++)
#pragma unroll
            for (int c = 0; c < 4; c++) acc[a][b][c] = 0.f;

    const int niter = K >> 5;
    float4 pa[4], pw[2];

#pragma unroll
    for (int p = 0; p < 4; p++) {
        int idx = tid + p * 256;
        int r = idx >> 3, c = (idx & 7) << 2;
        pa[p] = *reinterpret_cast<const float4*>(A + (size_t)(bm + r) * K + c);
    }
#pragma unroll
    for (int p = 0; p < 2; p++) {
        int idx = tid + p * 256;
        int r = idx >> 3, c = (idx & 7) << 2;
        int wr = bn + r;
        pw[p] = (wr < Mo) ? *reinterpret_cast<const float4*>(W + (size_t)wr * K + c)
                          : make_float4(0.f, 0.f, 0.f, 0.f);
    }

    for (int it = 0; it < niter; it++) {
#pragma unroll
        for (int p = 0; p < 4; p++) {
            int idx = tid + p * 256;
            int r = idx >> 3, c = (idx & 7) << 2;
            uint32_t* d = &As[r * 36 + c];
            d[0] = f2tf(pa[p].x); d[1] = f2tf(pa[p].y);
            d[2] = f2tf(pa[p].z); d[3] = f2tf(pa[p].w);
        }
#pragma unroll
        for (int p = 0; p < 2; p++) {
            int idx = tid + p * 256;
            int r = idx >> 3, c = (idx & 7) << 2;
            uint32_t* d = &Ws[r * 36 + c];
            d[0] = f2tf(pw[p].x); d[1] = f2tf(pw[p].y);
            d[2] = f2tf(pw[p].z); d[3] = f2tf(pw[p].w);
        }
        __syncthreads();

        if (it + 1 < niter) {
            int k0 = (it + 1) << 5;
#pragma unroll
            for (int p = 0; p < 4; p++) {
                int idx = tid + p * 256;
                int r = idx >> 3, c = (idx & 7) << 2;
                pa[p] = *reinterpret_cast<const float4*>(A + (size_t)(bm + r) * K + k0 + c);
            }
#pragma unroll
            for (int p = 0; p < 2; p++) {
                int idx = tid + p * 256;
                int r = idx >> 3, c = (idx & 7) << 2;
                int wr = bn + r;
                pw[p] = (wr < Mo) ? *reinterpret_cast<const float4*>(W + (size_t)wr * K + k0 + c)
                                  : make_float4(0.f, 0.f, 0.f, 0.f);
            }
        }

#pragma unroll
        for (int ks = 0; ks < 4; ks++) {
            const int kb = ks * 8;
            LOAD_FRAGS(As, Ws, kb)
#pragma unroll
            for (int fm = 0; fm < 2; fm++)
#pragma unroll
                for (int fn = 0; fn < 4; fn++) MMA_TF32(acc[fm][fn], af[fm], bf[fn]);
        }
        __syncthreads();
    }

#pragma unroll
    for (int fm = 0; fm < 2; fm++) {
        int rbase = bm + warp_m * 32 + fm * 16 + gid;
#pragma unroll
        for (int fn = 0; fn < 4; fn++) {
            int c = bn + warp_n * 32 + fn * 8 + (tg << 1);
            if (c < Mo) {
                float bc0 = bias[c], bc1 = bias[c + 1];
#pragma unroll
                for (int h = 0; h < 2; h++) {
                    int row = rbase + h * 8;
                    if (row < Nstore) {
                        float v0 = acc[fm][fn][h * 2 + 0] + bc0;
                        float v1 = acc[fm][fn][h * 2 + 1] + bc1;
                        if (add) {
                            float2 ad = *reinterpret_cast<const float2*>(add + (size_t)row * Mo + c);
                            v0 += ad.x; v1 += ad.y;
                        }
                        if (relu) { v0 = fmaxf(v0, 0.f); v1 = fmaxf(v1, 0.f); }
                        *reinterpret_cast<float2*>(C + (size_t)row * Mo + c) = make_float2(v0, v1);
                    }
                }
            }
        }
    }
}

// ---------------- fused QKV GEMM: grid (9, 99) ----------------
// blockIdx.x/3 selects which of {Wq,Wk,Wv}; (blockIdx.x%3)*64 is the N tile.
__global__ __launch_bounds__(256) void qkv_gemm_kernel(
    const float* __restrict__ A,
    const float* __restrict__ Wq, const float* __restrict__ Wk, const float* __restrict__ Wv,
    const float* __restrict__ bq, const float* __restrict__ bk, const float* __restrict__ bv,
    float* __restrict__ Qo, float* __restrict__ Ko, float* __restrict__ Vo)
{
    __shared__ __align__(16) uint32_t As[128*36];
    __shared__ __align__(16) uint32_t Ws[64*36];
    const int sel = blockIdx.x / 3;
    const int bn  = (blockIdx.x % 3) * 64;
    const float* W    = (sel == 0) ? Wq : (sel == 1) ? Wk : Wv;
    const float* bias = (sel == 0) ? bq : (sel == 1) ? bk : bv;
    float* C          = (sel == 0) ? Qo : (sel == 1) ? Ko : Vo;

    const int bm = blockIdx.y * 128;
    const int tid  = threadIdx.x;
    const int lane = tid & 31, wid = tid >> 5;
    const int warp_m = wid >> 1, warp_n = wid & 1;
    const int gid = lane >> 2, tg = lane & 3;

    float acc[2][4][4];
#pragma unroll
    for (int a = 0; a < 2; a++)
#pragma unroll
        for (int b = 0; b < 4; b++)
#pragma unroll
            for (int c = 0; c < 4; c++) acc[a][b][c] = 0.f;

    float4 pa[4], pw[2];
#pragma unroll
    for (int p = 0; p < 4; p++) {
        int idx = tid + p * 256;
        int r = idx >> 3, c = (idx & 7) << 2;
        pa[p] = *reinterpret_cast<const float4*>(A + (size_t)(bm + r) * D_ + c);
    }
#pragma unroll
    for (int p = 0; p < 2; p++) {
        int idx = tid + p * 256;
        int r = idx >> 3, c = (idx & 7) << 2;
        pw[p] = *reinterpret_cast<const float4*>(W + (size_t)(bn + r) * D_ + c);
    }

    for (int it = 0; it < 6; it++) {
#pragma unroll
        for (int p = 0; p < 4; p++) {
            int idx = tid + p * 256;
            int r = idx >> 3, c = (idx & 7) << 2;
            uint32_t* d = &As[r * 36 + c];
            d[0] = f2tf(pa[p].x); d[1] = f2tf(pa[p].y);
            d[2] = f2tf(pa[p].z); d[3] = f2tf(pa[p].w);
        }
#pragma unroll
        for (int p = 0; p < 2; p++) {
            int idx = tid + p * 256;
            int r = idx >> 3, c = (idx & 7) << 2;
            uint32_t* d = &Ws[r * 36 + c];
            d[0] = f2tf(pw[p].x); d[1] = f2tf(pw[p].y);
            d[2] = f2tf(pw[p].z); d[3] = f2tf(pw[p].w);
        }
        __syncthreads();

        if (it + 1 < 6) {
            int k0 = (it + 1) << 5;
#pragma unroll
            for (int p = 0; p < 4; p++) {
                int idx = tid + p * 256;
                int r = idx >> 3, c = (idx & 7) << 2;
                pa[p] = *reinterpret_cast<const float4*>(A + (size_t)(bm + r) * D_ + k0 + c);
            }
#pragma unroll
            for (int p = 0; p < 2; p++) {
                int idx = tid + p * 256;
                int r = idx >> 3, c = (idx & 7) << 2;
                pw[p] = *reinterpret_cast<const float4*>(W + (size_t)(bn + r) * D_ + k0 + c);
            }
        }

#pragma unroll
        for (int ks = 0; ks < 4; ks++) {
            const int kb = ks * 8;
            LOAD_FRAGS(As, Ws, kb)
#pragma unroll
            for (int fm = 0; fm < 2; fm++)
#pragma unroll
                for (int fn = 0; fn < 4; fn++) MMA_TF32(acc[fm][fn], af[fm], bf[fn]);
        }
        __syncthreads();
    }

#pragma unroll
    for (int fm = 0; fm < 2; fm++) {
        int rbase = bm + warp_m * 32 + fm * 16 + gid;
#pragma unroll
        for (int fn = 0; fn < 4; fn++) {
            int c = bn + warp_n * 32 + fn * 8 + (tg << 1);
            float bc0 = bias[c], bc1 = bias[c + 1];
#pragma unroll
            for (int h = 0; h < 2; h++) {
                int row = rbase + h * 8;
                *reinterpret_cast<float2*>(C + (size_t)row * D_ + c) =
                    make_float2(acc[fm][fn][h * 2 + 0] + bc0, acc[fm][fn][h * 2 + 1] + bc1);
            }
        }
    }
}

// ---------------- FAVOR feature-map GEMM (offs fused in-block) ----------------
// grid (2, NTP/128, 6): z%3 = head, z/3 selects (q->Qp) or (k->Kp).
__global__ __launch_bounds__(256) void favor_gemm_kernel(
    const float* __restrict__ Qin, const float* __restrict__ Kin,
    const float* __restrict__ omT,
    float* __restrict__ QPhi, float* __restrict__ KPhi)
{
    __shared__ __align__(16) uint32_t As[128*36];
    __shared__ __align__(16) uint32_t Ws[64*36];
    __shared__ float rowsq[128];
    const int hh  = blockIdx.z % 3;
    const int sel = blockIdx.z / 3;
    const float* A = (sel ? Kin : Qin) + hh * DH_;
    float* Phi     = sel ? KPhi : QPhi;

    const int bm = blockIdx.y * 128;
    const int bn = blockIdx.x * 64;
    const int tid  = threadIdx.x;
    const int lane = tid & 31, wid = tid >> 5;
    const int warp_m = wid >> 1, warp_n = wid & 1;
    const int gid = lane >> 2, tg = lane & 3;

    if (tid < 128) rowsq[tid] = 0.f;
    __syncthreads();

    float acc[2][4][4];
#pragma unroll
    for (int a = 0; a < 2; a++)
#pragma unroll
        for (int b = 0; b < 4; b++)
#pragma unroll
            for (int c = 0; c < 4; c++) acc[a][b][c] = 0.f;

    for (int it = 0; it < 2; it++) {
        const int k0 = it << 5;
#pragma unroll
        for (int p = 0; p < 4; p++) {
            int idx = tid + p * 256;
            int r = idx >> 3, c = (idx & 7) << 2;
            float4 v = *reinterpret_cast<const float4*>(A + (size_t)(bm + r) * D_ + k0 + c);
            atomicAdd(&rowsq[r], v.x * v.x + v.y * v.y + v.z * v.z + v.w * v.w);
            uint32_t* d = &As[r * 36 + c];
            d[0] = f2tf(v.x); d[1] = f2tf(v.y); d[2] = f2tf(v.z); d[3] = f2tf(v.w);
        }
#pragma unroll
        for (int p = 0; p < 2; p++) {
            int idx = tid + p * 256;
            int r = idx >> 3, c = (idx & 7) << 2;
            float4 v = *reinterpret_cast<const float4*>(omT + (size_t)(bn + r) * DH_ + k0 + c);
            uint32_t* d = &Ws[r * 36 + c];
            d[0] = f2tf(v.x); d[1] = f2tf(v.y); d[2] = f2tf(v.z); d[3] = f2tf(v.w);
        }
        __syncthreads();
#pragma unroll
        for (int ks = 0; ks < 4; ks++) {
            const int kb = ks * 8;
            LOAD_FRAGS(As, Ws, kb)
#pragma unroll
            for (int fm = 0; fm < 2; fm++)
#pragma unroll
                for (int fn = 0; fn < 4; fn++) MMA_TF32(acc[fm][fn], af[fm], bf[fn]);
        }
        __syncthreads();
    }

    // epilogue: Phi[t*768 + h*256 + m] = exp(u - off)/16 ; [+128+m] = exp(-u - off)/16
#pragma unroll
    for (int fm = 0; fm < 2; fm++) {
        int lbase = warp_m * 32 + fm * 16 + gid;
#pragma unroll
        for (int fn = 0; fn < 4; fn++) {
            int m = bn + warp_n * 32 + fn * 8 + (tg << 1);
#pragma unroll
            for (int h = 0; h < 2; h++) {
                int lr = lbase + h * 8;
                int t = bm + lr;
                if (t < NT_) {
                    float off = 0.0625f * rowsq[lr];
                    float u0 = acc[fm][fn][h * 2 + 0];
                    float u1 = acc[fm][fn][h * 2 + 1];
                    float2 e1 = make_float2(expf(u0 - off) * 0.0625f, expf(u1 - off) * 0.0625f);
                    float2 e2 = make_float2(expf(-u0 - off) * 0.0625f, expf(-u1 - off) * 0.0625f);
                    size_t base = (size_t)t * 768 + hh * 256 + m;
                    *reinterpret_cast<float2*>(Phi + base)       = e1;
                    *reinterpret_cast<float2*>(Phi + base + 128) = e2;
                }
            }
        }
    }
}

// ---------------- attention apply GEMM with fused Z ----------------
// grid (2, B*H): per (b,h) GEMM M=197, N=64, K=256. Z computed in-block.
__global__ __launch_bounds__(256) void attn_gemm_kernel(
    const float* __restrict__ Qp, const float* __restrict__ KVt,
    const float* __restrict__ Ks, float* __restrict__ O)
{
    __shared__ __align__(16) uint32_t As[128*36];
    __shared__ __align__(16) uint32_t Ws[64*36];
    __shared__ float Kss[256];
    __shared__ float zacc[128];
    const int bh = blockIdx.y;
    const int b = bh / 3, hh = bh % 3;
    const float* A = Qp + (size_t)b * L_ * 768 + hh * 256;
    const float* W = KVt + (size_t)bh * DH_ * TM_;

    const int bm = blockIdx.x * 128;
    const int tid  = threadIdx.x;
    const int lane = tid & 31, wid = tid >> 5;
    const int warp_m = wid >> 1, warp_n = wid & 1;
    const int gid = lane >> 2, tg = lane & 3;

    if (tid < 128) zacc[tid] = 0.f;
    Kss[tid] = Ks[(size_t)bh * TM_ + tid];
    __syncthreads();

    float acc[2][4][4];
#pragma unroll
    for (int a = 0; a < 2; a++)
#pragma unroll
        for (int c2 = 0; c2 < 4; c2++)
#pragma unroll
            for (int c = 0; c < 4; c++) acc[a][c2][c] = 0.f;

    float zpart[4] = {0.f, 0.f, 0.f, 0.f};

    for (int it = 0; it < 8; it++) {
        const int k0 = it << 5;
#pragma unroll
        for (int p = 0; p < 4; p++) {
            int idx = tid + p * 256;
            int r = idx >> 3, c = (idx & 7) << 2;
            int lr = bm + r;
            float4 v = (lr < L_) ? *reinterpret_cast<const float4*>(A + (size_t)lr * 768 + k0 + c)
                                 : make_float4(0.f, 0.f, 0.f, 0.f);
            zpart[p] += v.x * Kss[k0 + c] + v.y * Kss[k0 + c + 1]
                      + v.z * Kss[k0 + c + 2] + v.w * Kss[k0 + c + 3];
            uint32_t* d = &As[r * 36 + c];
            d[0] = f2tf(v.x); d[1] = f2tf(v.y); d[2] = f2tf(v.z); d[3] = f2tf(v.w);
        }
#pragma unroll
        for (int p = 0; p < 2; p++) {
            int idx = tid + p * 256;
            int r = idx >> 3, c = (idx & 7) << 2;
            float4 v = *reinterpret_cast<const float4*>(W + (size_t)r * TM_ + k0 + c);
            uint32_t* d = &Ws[r * 36 + c];
            d[0] = f2tf(v.x); d[1] = f2tf(v.y); d[2] = f2tf(v.z); d[3] = f2tf(v.w);
        }
        __syncthreads();
#pragma unroll
        for (int ks = 0; ks < 4; ks++) {
            const int kb = ks * 8;
            LOAD_FRAGS(As, Ws, kb)
#pragma unroll
            for (int fm = 0; fm < 2; fm++)
#pragma unroll
                for (int fn = 0; fn < 4; fn++) MMA_TF32(acc[fm][fn], af[fm], bf[fn]);
        }
        __syncthreads();
    }

    // finish Z: width-8 shfl reduce (8 consecutive threads share a row), then atomic
#pragma unroll
    for (int p = 0; p < 4; p++) {
        float val = zpart[p];
        val += __shfl_down_sync(0xffffffffu, val, 4, 8);
        val += __shfl_down_sync(0xffffffffu, val, 2, 8);
        val += __shfl_down_sync(0xffffffffu, val, 1, 8);
        if ((tid & 7) == 0) atomicAdd(&zacc[(tid + p * 256) >> 3], val);
    }
    __syncthreads();

#pragma unroll
    for (int fm = 0; fm < 2; fm++) {
        int lbase = warp_m * 32 + fm * 16 + gid;
#pragma unroll
        for (int fn = 0; fn < 4; fn++) {
            int c = warp_n * 32 + fn * 8 + (tg << 1);
#pragma unroll
            for (int h = 0; h < 2; h++) {
                int lr2 = lbase + h * 8;
                int lrow = bm + lr2;
                if (lrow < L_) {
                    int t = b * L_ + lrow;
                    float z = 1.f / (zacc[lr2] + 1e-6f);
                    float v0 = acc[fm][fn][h * 2 + 0] * z;
                    float v1 = acc[fm][fn][h * 2 + 1] * z;
                    *reinterpret_cast<float2*>(O + (size_t)t * D_ + hh * 64 + c) = make_float2(v0, v1);
                }
            }
        }
    }
}

// ---------------- omega transpose + scale, ALL layers at once ----------------
__global__ void omt_all_kernel(const float* __restrict__ om, float* __restrict__ omT)
{
    int i = blockIdx.x * 256 + threadIdx.x;   // 12*8192
    int layer = i >> 13, w = i & 8191;
    int m = w >> 6, d = w & 63;
    omT[i] = om[(size_t)layer * 8192 + d * MM_ + m] * 0.35355339059327373f;
}

// ---------------- KVt = (Kp^T @ V) transposed, plus Ksum ----------------
// 4 tokens per sync round, float4 smem reads.
__global__ void kv_kernel(const float* __restrict__ Kp, const float* __restrict__ V,
                          float* __restrict__ KVt, float* __restrict__ Ks)
{
    int b = blockIdx.x, h = blockIdx.y, m = threadIdx.x;  // 256 threads
    __shared__ __align__(16) float vs[4][64];
    float acc[64];
#pragma unroll
    for (int d = 0; d < 64; d++) acc[d] = 0.f;
    float ks = 0.f;
    const int j = m >> 6, d0 = m & 63;
    for (int l0 = 0; l0 < L_; l0 += 4) {
        int lj = l0 + j;
        if (lj < L_) vs[j][d0] = V[(size_t)(b * L_ + lj) * D_ + h * DH_ + d0];
        __syncthreads();
        int lim = L_ - l0; if (lim > 4) lim = 4;
        for (int jj = 0; jj < lim; jj++) {
            float kp = Kp[(size_t)(b * L_ + l0 + jj) * 768 + h * 256 + m];
            ks += kp;
#pragma unroll
            for (int d4 = 0; d4 < 16; d4++) {
                float4 v4 = *reinterpret_cast<const float4*>(&vs[jj][d4 * 4]);
                acc[d4 * 4 + 0] += kp * v4.x;
                acc[d4 * 4 + 1] += kp * v4.y;
                acc[d4 * 4 + 2] += kp * v4.z;
                acc[d4 * 4 + 3] += kp * v4.w;
            }
        }
        __syncthreads();
    }
    size_t base = (size_t)(b * H_ + h) * DH_ * TM_;
#pragma unroll
    for (int d = 0; d < 64; d++) KVt[base + (size_t)d * TM_ + m] = acc[d];
    Ks[(size_t)(b * H_ + h) * TM_ + m] = ks;
}

// ---------------- im2col for 16x16/stride16 conv ----------------
__global__ void im2col_kernel(const float* __restrict__ x, float* __restrict__ out)
{
    int o = blockIdx.x * 256 + threadIdx.x;
    if (o >= NP_ * 768) return;
    int kk = o % 768;
    int t  = o / 768;
    int b = t / 196, p = t % 196;
    int gh = p / 14, gw = p % 14;
    int c = kk / 256, r = kk % 256;
    int pp = r / 16, qq = r % 16;
    out[o] = x[((size_t)(b * 3 + c) * 224 + gh * 16 + pp) * 224 + gw * 16 + qq];
}

// ---------------- LayerNorm helpers (192 threads/block) ----------------
__device__ __forceinline__ void block_stats192(float x, float* sh, float& mu, float& rs)
{
    float s = x, ss = x * x;
#pragma unroll
    for (int o = 16; o; o >>= 1) {
        s  += __shfl_down_sync(0xffffffffu, s,  o);
        ss += __shfl_down_sync(0xffffffffu, ss, o);
    }
    int w = threadIdx.x >> 5;
    if ((threadIdx.x & 31) == 0) { sh[w] = s; sh[6 + w] = ss; }
    __syncthreads();
    if (threadIdx.x == 0) {
        float a = 0.f, b = 0.f;
        for (int i = 0; i < 6; i++) { a += sh[i]; b += sh[6 + i]; }
        float m = a * (1.f / 192.f);
        float v = b * (1.f / 192.f) - m * m;
        sh[0] = m; sh[1] = rsqrtf(v + 1e-5f);
    }
    __syncthreads();
    mu = sh[0]; rs = sh[1];
}

__global__ void ln_kernel(const float* __restrict__ X, const float* __restrict__ g,
                          const float* __restrict__ bb, float* __restrict__ Y)
{
    int row = blockIdx.x, tid = threadIdx.x;
    __shared__ float sh[12];
    float x = X[(size_t)row * D_ + tid];
    float mu, rs;
    block_stats192(x, sh, mu, rs);
    Y[(size_t)row * D_ + tid] = (x - mu) * rs * g[tid] + bb[tid];
}

__global__ void dln_kernel(const float* __restrict__ X,
                           const float* __restrict__ g1, const float* __restrict__ b1,
                           const float* __restrict__ g2, const float* __restrict__ b2,
                           float* __restrict__ Y)
{
    int row = blockIdx.x, tid = threadIdx.x;
    __shared__ float sh[12];
    float x = X[(size_t)row * D_ + tid];
    float mu, rs;
    block_stats192(x, sh, mu, rs);
    float y = (x - mu) * rs * g1[tid] + b1[tid];
    __syncthreads();
    block_stats192(y, sh, mu, rs);
    Y[(size_t)row * D_ + tid] = (y - mu) * rs * g2[tid] + b2[tid];
}

__global__ void ln_patch_kernel(const float* __restrict__ T, const float* __restrict__ g,
                                const float* __restrict__ bb, const float* __restrict__ pos,
                                float* __restrict__ XC)
{
    int row = blockIdx.x, tid = threadIdx.x;   // row in [0, NP_)
    __shared__ float sh[12];
    float x = T[(size_t)row * D_ + tid];
    float mu, rs;
    block_stats192(x, sh, mu, rs);
    int b = row / 196, p = row % 196;
    float v = (x - mu) * rs * g[tid] + bb[tid] + pos[(size_t)(1 + p) * D_ + tid];
    XC[((size_t)b * L_ + 1 + p) * D_ + tid] = v;
}

__global__ void cls_kernel(const float* __restrict__ cls, const float* __restrict__ pos,
                           float* __restrict__ XC)
{
    int b = blockIdx.x, tid = threadIdx.x;
    XC[(size_t)b * L_ * D_ + tid] = cls[tid] + pos[tid];
}

// ---------------- mean pool over sequence ----------------
__global__ void pool_kernel(const float* __restrict__ XC, float* __restrict__ P)
{
    int b = blockIdx.x, tid = threadIdx.x;
    float s = 0.f;
    for (int l = 0; l < L_; l++) s += XC[((size_t)b * L_ + l) * D_ + tid];
    P[(size_t)b * D_ + tid] = s * (1.f / 197.f);
}

// ---------------- launcher ----------------
extern "C" void kernel_launch(void* const* d_in, const int* in_sizes, int n_in,
                              void* d_out, int out_size)
{
    (void)in_sizes; (void)n_in; (void)out_size;
    const float* x    = (const float*)d_in[0];
    const float* pw   = (const float*)d_in[1];
    const float* pb   = (const float*)d_in[2];
    const float* peg  = (const float*)d_in[3];
    const float* peb  = (const float*)d_in[4];
    const float* cls  = (const float*)d_in[5];
    const float* pos  = (const float*)d_in[6];
    const float* Wq   = (const float*)d_in[7];
    const float* bq   = (const float*)d_in[8];
    const float* Wk   = (const float*)d_in[9];
    const float* bk   = (const float*)d_in[10];
    const float* Wv   = (const float*)d_in[11];
    const float* bv   = (const float*)d_in[12];
    const float* Wo   = (const float*)d_in[13];
    const float* bo   = (const float*)d_in[14];
    const float* l1g  = (const float*)d_in[15];
    const float* l1b  = (const float*)d_in[16];
    const float* l2g  = (const float*)d_in[17];
    const float* l2b  = (const float*)d_in[18];
    const float* lbg  = (const float*)d_in[19];
    const float* lbb  = (const float*)d_in[20];
    const float* W1   = (const float*)d_in[21];
    const float* b1   = (const float*)d_in[22];
    const float* W2   = (const float*)d_in[23];
    const float* b2   = (const float*)d_in[24];
    const float* om   = (const float*)d_in[25];
    const float* hw   = (const float*)d_in[26];
    const float* hb   = (const float*)d_in[27];
    float* out = (float*)d_out;

    float *xc, *q, *k, *v, *Qp, *Kp, *KVt, *Ks, *at, *tp, *h1, *pl, *im, *omT;
    cudaGetSymbolAddress((void**)&xc,  g_xc);
    cudaGetSymbolAddress((void**)&q,   g_q);
    cudaGetSymbolAddress((void**)&k,   g_k);
    cudaGetSymbolAddress((void**)&v,   g_v);
    cudaGetSymbolAddress((void**)&Qp,  g_Qp);
    cudaGetSymbolAddress((void**)&Kp,  g_Kp);
    cudaGetSymbolAddress((void**)&KVt, g_KVt);
    cudaGetSymbolAddress((void**)&Ks,  g_Ks);
    cudaGetSymbolAddress((void**)&at,  g_at);
    cudaGetSymbolAddress((void**)&tp,  g_tp);
    cudaGetSymbolAddress((void**)&h1,  g_h1);
    cudaGetSymbolAddress((void**)&pl,  g_pl);
    cudaGetSymbolAddress((void**)&im,  g_im);
    cudaGetSymbolAddress((void**)&omT, g_omT);

    // ---- one-time: all-layer omega transpose; patch embedding ----
    omt_all_kernel<<<(12 * 8192) / 256, 256>>>(om, omT);
    {
        int tot = NP_ * 768;
        im2col_kernel<<<(tot + 255) / 256, 256>>>(x, im);
        tgemm_kernel<<<dim3(3, NP_ / 128), 256>>>(im, pw, pb, nullptr, q, 768, D_, NP_, 0);
        ln_patch_kernel<<<NP_, 192>>>(q, peg, peb, pos, xc);
        cls_kernel<<<B_, 192>>>(cls, pos, xc);
    }

    const dim3 gD(3, NTP_ / 128);    // Mo=192
    const dim3 gF(12, NTP_ / 128);   // Mo=768

    for (int i = 0; i < 12; i++) {
        qkv_gemm_kernel<<<dim3(9, NTP_ / 128), 256>>>(
            xc,
            Wq + (size_t)i * D_ * D_, Wk + (size_t)i * D_ * D_, Wv + (size_t)i * D_ * D_,
            bq + i * D_, bk + i * D_, bv + i * D_, q, k, v);
        favor_gemm_kernel<<<dim3(2, NTP_ / 128, 6), 256>>>(q, k, omT + (size_t)i * 8192, Qp, Kp);
        kv_kernel<<<dim3(B_, H_), 256>>>(Kp, v, KVt, Ks);
        attn_gemm_kernel<<<dim3(2, B_ * H_), 256>>>(Qp, KVt, Ks, at);
        // xc_new_pre = xc + attn @ Wo^T + bo
        tgemm_kernel<<<gD, 256>>>(at, Wo + (size_t)i * D_ * D_, bo + i * D_, xc, tp, D_, D_, NTP_, 0);
        ln_kernel<<<NT_, 192>>>(tp, l1g + i * D_, l1b + i * D_, xc);
        // MLP
        tgemm_kernel<<<gF, 256>>>(xc, W1 + (size_t)i * FF_ * D_, b1 + i * FF_, nullptr, h1, D_, FF_, NTP_, 1);
        tgemm_kernel<<<gD, 256>>>(h1, W2 + (size_t)i * D_ * FF_, b2 + i * D_, xc, tp, FF_, D_, NTP_, 0);
        dln_kernel<<<NT_, 192>>>(tp, l2g + i * D_, l2b + i * D_, lbg + i * D_, lbb + i * D_, xc);

        if (i == 3 || i == 7 || i == 11) {
            int j = (i == 3) ? 0 : (i == 7) ? 1 : 2;
            pool_kernel<<<B_, 192>>>(xc, pl);
            tgemm_kernel<<<dim3(16, 1), 256>>>(pl, hw + (size_t)j * NCLS_ * D_, hb + j * NCLS_,
                                               nullptr, out + (size_t)j * B_ * NCLS_, D_, NCLS_, B_, 0);
        }
    }
}

// round 9
// speedup vs baseline: 2.8770x; 1.1184x over previous
#include <cuda_runtime.h>
#include <math.h>
#include <stdint.h>

#define B_    64
#define L_    197
#define D_    192
#define H_    3
#define DH_   64
#define MM_   128
#define TM_   256           // 2M
#define NT_   (B_*L_)       // 12608
#define NTP_  12672         // 99 * 128 (padded rows)
#define FF_   768
#define NCLS_ 1000
#define NP_   (B_*196)      // 12544
#define KVSZ  (B_*H_*DH_*TM_)   // 3145728
#define KSSZ  (B_*H_*TM_)       // 49152

// ---------------- scratch (static device globals; zero-initialized) ----------------
__device__ float g_xc [NTP_*D_];
__device__ float g_q  [NTP_*D_];
__device__ float g_k  [NTP_*D_];
__device__ float g_v  [NTP_*D_];
__device__ float g_Qp [NT_*H_*TM_];
__device__ float g_Kp [NT_*H_*TM_];
__device__ float g_KVp[4*KVSZ];          // 4 split partials, [s][bh][d][m]
__device__ float g_Ksp[4*KSSZ];          // [s][bh][m]
__device__ float g_at [NTP_*D_];
__device__ float g_tp [NTP_*D_];
__device__ float g_h1 [NTP_*FF_];
__device__ float g_pl [128*D_];
__device__ float g_im [NP_*768];
__device__ float g_omT[12*MM_*DH_];      // per-layer transposed, pre-scaled omega

__device__ __forceinline__ uint32_t f2tf(float f) {
    uint32_t o; asm("cvt.rna.tf32.f32 %0, %1;" : "=r"(o) : "f"(f)); return o;
}

#define MMA_TF32(acc, af, bf)                                               \
    asm volatile(                                                           \
        "mma.sync.aligned.m16n8k8.row.col.f32.tf32.tf32.f32 "               \
        "{%0,%1,%2,%3}, {%4,%5,%6,%7}, {%8,%9}, {%0,%1,%2,%3};\n"           \
        : "+f"(acc[0]), "+f"(acc[1]), "+f"(acc[2]), "+f"(acc[3])            \
        : "r"(af[0]), "r"(af[1]), "r"(af[2]), "r"(af[3]),                   \
          "r"(bf[0]), "r"(bf[1]))

// fragment loads from smem (pitch 36, conflict-free), 2x4 warp tile
#define LOAD_FRAGS(As, Ws, kb)                                              \
    uint32_t af[2][4], bf[4][2];                                            \
    _Pragma("unroll")                                                       \
    for (int fm = 0; fm < 2; fm++) {                                        \
        int r0 = warp_m * 32 + fm * 16 + gid;                               \
        af[fm][0] = As[r0 * 36 + kb + tg];                                  \
        af[fm][1] = As[(r0 + 8) * 36 + kb + tg];                            \
        af[fm][2] = As[r0 * 36 + kb + tg + 4];                              \
        af[fm][3] = As[(r0 + 8) * 36 + kb + tg + 4];                        \
    }                                                                       \
    _Pragma("unroll")                                                       \
    for (int fn = 0; fn < 4; fn++) {                                        \
        int n = warp_n * 32 + fn * 8 + gid;                                 \
        bf[fn][0] = Ws[n * 36 + kb + tg];                                   \
        bf[fn][1] = Ws[n * 36 + kb + tg + 4];                               \
    }

// ---------------- TF32 tensor-core GEMM (generic) ----------------
__global__ __launch_bounds__(256) void tgemm_kernel(
    const float* __restrict__ A, const float* __restrict__ W,
    const float* __restrict__ bias, const float* __restrict__ add,
    float* __restrict__ C, int K, int Mo, int Nstore, int relu)
{
    __shared__ __align__(16) uint32_t As[128*36];
    __shared__ __align__(16) uint32_t Ws[64*36];
    const int bm = blockIdx.y * 128;
    const int bn = blockIdx.x * 64;
    const int tid  = threadIdx.x;
    const int lane = tid & 31, wid = tid >> 5;
    const int warp_m = wid >> 1, warp_n = wid & 1;
    const int gid = lane >> 2, tg = lane & 3;

    float acc[2][4][4];
#pragma unroll
    for (int a = 0; a < 2; a++)
#pragma unroll
        for (int b = 0; b < 4; b++)
#pragma unroll
            for (int c = 0; c < 4; c++) acc[a][b][c] = 0.f;

    const int niter = K >> 5;
    float4 pa[4], pw[2];

#pragma unroll
    for (int p = 0; p < 4; p++) {
        int idx = tid + p * 256;
        int r = idx >> 3, c = (idx & 7) << 2;
        pa[p] = *reinterpret_cast<const float4*>(A + (size_t)(bm + r) * K + c);
    }
#pragma unroll
    for (int p = 0; p < 2; p++) {
        int idx = tid + p * 256;
        int r = idx >> 3, c = (idx & 7) << 2;
        int wr = bn + r;
        pw[p] = (wr < Mo) ? *reinterpret_cast<const float4*>(W + (size_t)wr * K + c)
                          : make_float4(0.f, 0.f, 0.f, 0.f);
    }

    for (int it = 0; it < niter; it++) {
#pragma unroll
        for (int p = 0; p < 4; p++) {
            int idx = tid + p * 256;
            int r = idx >> 3, c = (idx & 7) << 2;
            uint32_t* d = &As[r * 36 + c];
            d[0] = f2tf(pa[p].x); d[1] = f2tf(pa[p].y);
            d[2] = f2tf(pa[p].z); d[3] = f2tf(pa[p].w);
        }
#pragma unroll
        for (int p = 0; p < 2; p++) {
            int idx = tid + p * 256;
            int r = idx >> 3, c = (idx & 7) << 2;
            uint32_t* d = &Ws[r * 36 + c];
            d[0] = f2tf(pw[p].x); d[1] = f2tf(pw[p].y);
            d[2] = f2tf(pw[p].z); d[3] = f2tf(pw[p].w);
        }
        __syncthreads();

        if (it + 1 < niter) {
            int k0 = (it + 1) << 5;
#pragma unroll
            for (int p = 0; p < 4; p++) {
                int idx = tid + p * 256;
                int r = idx >> 3, c = (idx & 7) << 2;
                pa[p] = *reinterpret_cast<const float4*>(A + (size_t)(bm + r) * K + k0 + c);
            }
#pragma unroll
            for (int p = 0; p < 2; p++) {
                int idx = tid + p * 256;
                int r = idx >> 3, c = (idx & 7) << 2;
                int wr = bn + r;
                pw[p] = (wr < Mo) ? *reinterpret_cast<const float4*>(W + (size_t)wr * K + k0 + c)
                                  : make_float4(0.f, 0.f, 0.f, 0.f);
            }
        }

#pragma unroll
        for (int ks = 0; ks < 4; ks++) {
            const int kb = ks * 8;
            LOAD_FRAGS(As, Ws, kb)
#pragma unroll
            for (int fm = 0; fm < 2; fm++)
#pragma unroll
                for (int fn = 0; fn < 4; fn++) MMA_TF32(acc[fm][fn], af[fm], bf[fn]);
        }
        __syncthreads();
    }

#pragma unroll
    for (int fm = 0; fm < 2; fm++) {
        int rbase = bm + warp_m * 32 + fm * 16 + gid;
#pragma unroll
        for (int fn = 0; fn < 4; fn++) {
            int c = bn + warp_n * 32 + fn * 8 + (tg << 1);
            if (c < Mo) {
                float bc0 = bias[c], bc1 = bias[c + 1];
#pragma unroll
                for (int h = 0; h < 2; h++) {
                    int row = rbase + h * 8;
                    if (row < Nstore) {
                        float v0 = acc[fm][fn][h * 2 + 0] + bc0;
                        float v1 = acc[fm][fn][h * 2 + 1] + bc1;
                        if (add) {
                            float2 ad = *reinterpret_cast<const float2*>(add + (size_t)row * Mo + c);
                            v0 += ad.x; v1 += ad.y;
                        }
                        if (relu) { v0 = fmaxf(v0, 0.f); v1 = fmaxf(v1, 0.f); }
                        *reinterpret_cast<float2*>(C + (size_t)row * Mo + c) = make_float2(v0, v1);
                    }
                }
            }
        }
    }
}

// ---------------- fused QKV GEMM: grid (9, 99) ----------------
__global__ __launch_bounds__(256) void qkv_gemm_kernel(
    const float* __restrict__ A,
    const float* __restrict__ Wq, const float* __restrict__ Wk, const float* __restrict__ Wv,
    const float* __restrict__ bq, const float* __restrict__ bk, const float* __restrict__ bv,
    float* __restrict__ Qo, float* __restrict__ Ko, float* __restrict__ Vo)
{
    __shared__ __align__(16) uint32_t As[128*36];
    __shared__ __align__(16) uint32_t Ws[64*36];
    const int sel = blockIdx.x / 3;
    const int bn  = (blockIdx.x % 3) * 64;
    const float* W    = (sel == 0) ? Wq : (sel == 1) ? Wk : Wv;
    const float* bias = (sel == 0) ? bq : (sel == 1) ? bk : bv;
    float* C          = (sel == 0) ? Qo : (sel == 1) ? Ko : Vo;

    const int bm = blockIdx.y * 128;
    const int tid  = threadIdx.x;
    const int lane = tid & 31, wid = tid >> 5;
    const int warp_m = wid >> 1, warp_n = wid & 1;
    const int gid = lane >> 2, tg = lane & 3;

    float acc[2][4][4];
#pragma unroll
    for (int a = 0; a < 2; a++)
#pragma unroll
        for (int b = 0; b < 4; b++)
#pragma unroll
            for (int c = 0; c < 4; c++) acc[a][b][c] = 0.f;

    float4 pa[4], pw[2];
#pragma unroll
    for (int p = 0; p < 4; p++) {
        int idx = tid + p * 256;
        int r = idx >> 3, c = (idx & 7) << 2;
        pa[p] = *reinterpret_cast<const float4*>(A + (size_t)(bm + r) * D_ + c);
    }
#pragma unroll
    for (int p = 0; p < 2; p++) {
        int idx = tid + p * 256;
        int r = idx >> 3, c = (idx & 7) << 2;
        pw[p] = *reinterpret_cast<const float4*>(W + (size_t)(bn + r) * D_ + c);
    }

    for (int it = 0; it < 6; it++) {
#pragma unroll
        for (int p = 0; p < 4; p++) {
            int idx = tid + p * 256;
            int r = idx >> 3, c = (idx & 7) << 2;
            uint32_t* d = &As[r * 36 + c];
            d[0] = f2tf(pa[p].x); d[1] = f2tf(pa[p].y);
            d[2] = f2tf(pa[p].z); d[3] = f2tf(pa[p].w);
        }
#pragma unroll
        for (int p = 0; p < 2; p++) {
            int idx = tid + p * 256;
            int r = idx >> 3, c = (idx & 7) << 2;
            uint32_t* d = &Ws[r * 36 + c];
            d[0] = f2tf(pw[p].x); d[1] = f2tf(pw[p].y);
            d[2] = f2tf(pw[p].z); d[3] = f2tf(pw[p].w);
        }
        __syncthreads();

        if (it + 1 < 6) {
            int k0 = (it + 1) << 5;
#pragma unroll
            for (int p = 0; p < 4; p++) {
                int idx = tid + p * 256;
                int r = idx >> 3, c = (idx & 7) << 2;
                pa[p] = *reinterpret_cast<const float4*>(A + (size_t)(bm + r) * D_ + k0 + c);
            }
#pragma unroll
            for (int p = 0; p < 2; p++) {
                int idx = tid + p * 256;
                int r = idx >> 3, c = (idx & 7) << 2;
                pw[p] = *reinterpret_cast<const float4*>(W + (size_t)(bn + r) * D_ + k0 + c);
            }
        }

#pragma unroll
        for (int ks = 0; ks < 4; ks++) {
            const int kb = ks * 8;
            LOAD_FRAGS(As, Ws, kb)
#pragma unroll
            for (int fm = 0; fm < 2; fm++)
#pragma unroll
                for (int fn = 0; fn < 4; fn++) MMA_TF32(acc[fm][fn], af[fm], bf[fn]);
        }
        __syncthreads();
    }

#pragma unroll
    for (int fm = 0; fm < 2; fm++) {
        int rbase = bm + warp_m * 32 + fm * 16 + gid;
#pragma unroll
        for (int fn = 0; fn < 4; fn++) {
            int c = bn + warp_n * 32 + fn * 8 + (tg << 1);
            float bc0 = bias[c], bc1 = bias[c + 1];
#pragma unroll
            for (int h = 0; h < 2; h++) {
                int row = rbase + h * 8;
                *reinterpret_cast<float2*>(C + (size_t)row * D_ + c) =
                    make_float2(acc[fm][fn][h * 2 + 0] + bc0, acc[fm][fn][h * 2 + 1] + bc1);
            }
        }
    }
}

// ---------------- FAVOR feature-map GEMM (N=128 tile, offs fused) ----------------
// grid (99, 6): y%3 = head, y/3 selects (q->Qp) or (k->Kp). M-tile 128, N=128, K=64.
__global__ __launch_bounds__(256) void favor_gemm_kernel(
    const float* __restrict__ Qin, const float* __restrict__ Kin,
    const float* __restrict__ omT,
    float* __restrict__ QPhi, float* __restrict__ KPhi)
{
    __shared__ __align__(16) uint32_t As[128*36];
    __shared__ __align__(16) uint32_t Ws[128*36];
    __shared__ float rowsq[128];
    const int hh  = blockIdx.y % 3;
    const int sel = blockIdx.y / 3;
    const float* A = (sel ? Kin : Qin) + hh * DH_;
    float* Phi     = sel ? KPhi : QPhi;

    const int bm = blockIdx.x * 128;
    const int tid  = threadIdx.x;
    const int lane = tid & 31, wid = tid >> 5;
    const int warp_m = wid >> 1, warp_n = wid & 1;
    const int gid = lane >> 2, tg = lane & 3;

    if (tid < 128) rowsq[tid] = 0.f;
    __syncthreads();

    float acc[2][8][4];
#pragma unroll
    for (int a = 0; a < 2; a++)
#pragma unroll
        for (int b = 0; b < 8; b++)
#pragma unroll
            for (int c = 0; c < 4; c++) acc[a][b][c] = 0.f;

    for (int it = 0; it < 2; it++) {
        const int k0 = it << 5;
#pragma unroll
        for (int p = 0; p < 4; p++) {
            int idx = tid + p * 256;
            int r = idx >> 3, c = (idx & 7) << 2;
            float4 v = *reinterpret_cast<const float4*>(A + (size_t)(bm + r) * D_ + k0 + c);
            atomicAdd(&rowsq[r], v.x * v.x + v.y * v.y + v.z * v.z + v.w * v.w);
            uint32_t* d = &As[r * 36 + c];
            d[0] = f2tf(v.x); d[1] = f2tf(v.y); d[2] = f2tf(v.z); d[3] = f2tf(v.w);
        }
#pragma unroll
        for (int p = 0; p < 4; p++) {
            int idx = tid + p * 256;
            int r = idx >> 3, c = (idx & 7) << 2;
            float4 v = *reinterpret_cast<const float4*>(omT + (size_t)r * DH_ + k0 + c);
            uint32_t* d = &Ws[r * 36 + c];
            d[0] = f2tf(v.x); d[1] = f2tf(v.y); d[2] = f2tf(v.z); d[3] = f2tf(v.w);
        }
        __syncthreads();
#pragma unroll
        for (int ks = 0; ks < 4; ks++) {
            const int kb = ks * 8;
            uint32_t af[2][4], bf8[8][2];
#pragma unroll
            for (int fm = 0; fm < 2; fm++) {
                int r0 = warp_m * 32 + fm * 16 + gid;
                af[fm][0] = As[r0 * 36 + kb + tg];
                af[fm][1] = As[(r0 + 8) * 36 + kb + tg];
                af[fm][2] = As[r0 * 36 + kb + tg + 4];
                af[fm][3] = As[(r0 + 8) * 36 + kb + tg + 4];
            }
#pragma unroll
            for (int fn = 0; fn < 8; fn++) {
                int n = warp_n * 64 + fn * 8 + gid;
                bf8[fn][0] = Ws[n * 36 + kb + tg];
                bf8[fn][1] = Ws[n * 36 + kb + tg + 4];
            }
#pragma unroll
            for (int fm = 0; fm < 2; fm++)
#pragma unroll
                for (int fn = 0; fn < 8; fn++) MMA_TF32(acc[fm][fn], af[fm], bf8[fn]);
        }
        __syncthreads();
    }

#pragma unroll
    for (int fm = 0; fm < 2; fm++) {
        int lbase = warp_m * 32 + fm * 16 + gid;
#pragma unroll
        for (int fn = 0; fn < 8; fn++) {
            int m = warp_n * 64 + fn * 8 + (tg << 1);
#pragma unroll
            for (int h = 0; h < 2; h++) {
                int lr = lbase + h * 8;
                int t = bm + lr;
                if (t < NT_) {
                    float off = 0.0625f * rowsq[lr];
                    float u0 = acc[fm][fn][h * 2 + 0];
                    float u1 = acc[fm][fn][h * 2 + 1];
                    float2 e1 = make_float2(expf(u0 - off) * 0.0625f, expf(u1 - off) * 0.0625f);
                    float2 e2 = make_float2(expf(-u0 - off) * 0.0625f, expf(-u1 - off) * 0.0625f);
                    size_t base = (size_t)t * 768 + hh * 256 + m;
                    *reinterpret_cast<float2*>(Phi + base)       = e1;
                    *reinterpret_cast<float2*>(Phi + base + 128) = e2;
                }
            }
        }
    }
}

// ---------------- attention apply GEMM with fused Z and 4-way KV partial sum ----
// grid (2, B*H): per (b,h) GEMM M=197, N=64, K=256.
__global__ __launch_bounds__(256) void attn_gemm_kernel(
    const float* __restrict__ Qp, const float* __restrict__ KVp,
    const float* __restrict__ Ksp, float* __restrict__ O)
{
    __shared__ __align__(16) uint32_t As[128*36];
    __shared__ __align__(16) uint32_t Ws[64*36];
    __shared__ float Kss[256];
    __shared__ float zacc[128];
    const int bh = blockIdx.y;
    const int b = bh / 3, hh = bh % 3;
    const float* A = Qp + (size_t)b * L_ * 768 + hh * 256;
    const float* W = KVp + (size_t)bh * DH_ * TM_;

    const int bm = blockIdx.x * 128;
    const int tid  = threadIdx.x;
    const int lane = tid & 31, wid = tid >> 5;
    const int warp_m = wid >> 1, warp_n = wid & 1;
    const int gid = lane >> 2, tg = lane & 3;

    if (tid < 128) zacc[tid] = 0.f;
    {
        size_t kb = (size_t)bh * TM_ + tid;
        Kss[tid] = Ksp[kb] + Ksp[kb + KSSZ] + Ksp[kb + 2 * KSSZ] + Ksp[kb + 3 * KSSZ];
    }
    __syncthreads();

    float acc[2][4][4];
#pragma unroll
    for (int a = 0; a < 2; a++)
#pragma unroll
        for (int c2 = 0; c2 < 4; c2++)
#pragma unroll
            for (int c = 0; c < 4; c++) acc[a][c2][c] = 0.f;

    float zpart[4] = {0.f, 0.f, 0.f, 0.f};

    for (int it = 0; it < 8; it++) {
        const int k0 = it << 5;
#pragma unroll
        for (int p = 0; p < 4; p++) {
            int idx = tid + p * 256;
            int r = idx >> 3, c = (idx & 7) << 2;
            int lr = bm + r;
            float4 v = (lr < L_) ? *reinterpret_cast<const float4*>(A + (size_t)lr * 768 + k0 + c)
                                 : make_float4(0.f, 0.f, 0.f, 0.f);
            zpart[p] += v.x * Kss[k0 + c] + v.y * Kss[k0 + c + 1]
                      + v.z * Kss[k0 + c + 2] + v.w * Kss[k0 + c + 3];
            uint32_t* d = &As[r * 36 + c];
            d[0] = f2tf(v.x); d[1] = f2tf(v.y); d[2] = f2tf(v.z); d[3] = f2tf(v.w);
        }
#pragma unroll
        for (int p = 0; p < 2; p++) {
            int idx = tid + p * 256;
            int r = idx >> 3, c = (idx & 7) << 2;
            const float* wp = W + (size_t)r * TM_ + k0 + c;
            float4 v0 = *reinterpret_cast<const float4*>(wp);
            float4 v1 = *reinterpret_cast<const float4*>(wp + KVSZ);
            float4 v2 = *reinterpret_cast<const float4*>(wp + 2 * KVSZ);
            float4 v3 = *reinterpret_cast<const float4*>(wp + 3 * KVSZ);
            float4 v = make_float4(v0.x + v1.x + v2.x + v3.x, v0.y + v1.y + v2.y + v3.y,
                                   v0.z + v1.z + v2.z + v3.z, v0.w + v1.w + v2.w + v3.w);
            uint32_t* d = &Ws[r * 36 + c];
            d[0] = f2tf(v.x); d[1] = f2tf(v.y); d[2] = f2tf(v.z); d[3] = f2tf(v.w);
        }
        __syncthreads();
#pragma unroll
        for (int ks = 0; ks < 4; ks++) {
            const int kb = ks * 8;
            LOAD_FRAGS(As, Ws, kb)
#pragma unroll
            for (int fm = 0; fm < 2; fm++)
#pragma unroll
                for (int fn = 0; fn < 4; fn++) MMA_TF32(acc[fm][fn], af[fm], bf[fn]);
        }
        __syncthreads();
    }

    // finish Z: width-8 shfl reduce (8 consecutive threads share a row), then atomic
#pragma unroll
    for (int p = 0; p < 4; p++) {
        float val = zpart[p];
        val += __shfl_down_sync(0xffffffffu, val, 4, 8);
        val += __shfl_down_sync(0xffffffffu, val, 2, 8);
        val += __shfl_down_sync(0xffffffffu, val, 1, 8);
        if ((tid & 7) == 0) atomicAdd(&zacc[(tid + p * 256) >> 3], val);
    }
    __syncthreads();

#pragma unroll
    for (int fm = 0; fm < 2; fm++) {
        int lbase = warp_m * 32 + fm * 16 + gid;
#pragma unroll
        for (int fn = 0; fn < 4; fn++) {
            int c = warp_n * 32 + fn * 8 + (tg << 1);
#pragma unroll
            for (int h = 0; h < 2; h++) {
                int lr2 = lbase + h * 8;
                int lrow = bm + lr2;
                if (lrow < L_) {
                    int t = b * L_ + lrow;
                    float z = 1.f / (zacc[lr2] + 1e-6f);
                    float v0 = acc[fm][fn][h * 2 + 0] * z;
                    float v1 = acc[fm][fn][h * 2 + 1] * z;
                    *reinterpret_cast<float2*>(O + (size_t)t * D_ + hh * 64 + c) = make_float2(v0, v1);
                }
            }
        }
    }
}

// ---------------- omega transpose + scale, ALL layers at once ----------------
__global__ void omt_all_kernel(const float* __restrict__ om, float* __restrict__ omT)
{
    int i = blockIdx.x * 256 + threadIdx.x;   // 12*8192
    int layer = i >> 13, w = i & 8191;
    int m = w >> 6, d = w & 63;
    omT[i] = om[(size_t)layer * 8192 + d * MM_ + m] * 0.35355339059327373f;
}

// ---------------- KV partial: grid (B,H,4), ~50 tokens per split ----------------
__global__ void kv_kernel(const float* __restrict__ Kp, const float* __restrict__ V,
                          float* __restrict__ KVp, float* __restrict__ Ksp)
{
    int b = blockIdx.x, h = blockIdx.y, s = blockIdx.z, m = threadIdx.x;  // 256 threads
    __shared__ __align__(16) float vs[4][64];
    float acc[64];
#pragma unroll
    for (int d = 0; d < 64; d++) acc[d] = 0.f;
    float ks = 0.f;
    const int j = m >> 6, d0 = m & 63;
    const int lstart = s * 50;
    const int lend = (s == 3) ? L_ : lstart + 50;
    for (int l0 = lstart; l0 < lend; l0 += 4) {
        int lj = l0 + j;
        if (lj < lend) vs[j][d0] = V[(size_t)(b * L_ + lj) * D_ + h * DH_ + d0];
        __syncthreads();
        int lim = lend - l0; if (lim > 4) lim = 4;
        for (int jj = 0; jj < lim; jj++) {
            float kp = Kp[(size_t)(b * L_ + l0 + jj) * 768 + h * 256 + m];
            ks += kp;
#pragma unroll
            for (int d4 = 0; d4 < 16; d4++) {
                float4 v4 = *reinterpret_cast<const float4*>(&vs[jj][d4 * 4]);
                acc[d4 * 4 + 0] += kp * v4.x;
                acc[d4 * 4 + 1] += kp * v4.y;
                acc[d4 * 4 + 2] += kp * v4.z;
                acc[d4 * 4 + 3] += kp * v4.w;
            }
        }
        __syncthreads();
    }
    size_t base = (size_t)s * KVSZ + (size_t)(b * H_ + h) * DH_ * TM_;
#pragma unroll
    for (int d = 0; d < 64; d++) KVp[base + (size_t)d * TM_ + m] = acc[d];
    Ksp[(size_t)s * KSSZ + (size_t)(b * H_ + h) * TM_ + m] = ks;
}

// ---------------- im2col for 16x16/stride16 conv ----------------
__global__ void im2col_kernel(const float* __restrict__ x, float* __restrict__ out)
{
    int o = blockIdx.x * 256 + threadIdx.x;
    if (o >= NP_ * 768) return;
    int kk = o % 768;
    int t  = o / 768;
    int b = t / 196, p = t % 196;
    int gh = p / 14, gw = p % 14;
    int c = kk / 256, r = kk % 256;
    int pp = r / 16, qq = r % 16;
    out[o] = x[((size_t)(b * 3 + c) * 224 + gh * 16 + pp) * 224 + gw * 16 + qq];
}

// ---------------- warp-per-row LayerNorm family (256 thr = 8 rows/block) -------
__device__ __forceinline__ void warp_stats(float s, float ss, float& mu, float& rs)
{
#pragma unroll
    for (int o = 16; o; o >>= 1) {
        s  += __shfl_xor_sync(0xffffffffu, s,  o);
        ss += __shfl_xor_sync(0xffffffffu, ss, o);
    }
    mu = s * (1.f / 192.f);
    rs = rsqrtf(ss * (1.f / 192.f) - mu * mu + 1e-5f);
}

__global__ void lnw_kernel(const float* __restrict__ X, const float* __restrict__ g,
                           const float* __restrict__ bb, float* __restrict__ Y, int nrows)
{
    int w = (blockIdx.x * 256 + threadIdx.x) >> 5;
    int lane = threadIdx.x & 31;
    if (w >= nrows) return;
    const float* xr = X + (size_t)w * D_;
    float2 a[3];
    float s = 0.f, ss = 0.f;
#pragma unroll
    for (int j = 0; j < 3; j++) {
        a[j] = *reinterpret_cast<const float2*>(xr + j * 64 + lane * 2);
        s += a[j].x + a[j].y;
        ss += a[j].x * a[j].x + a[j].y * a[j].y;
    }
    float mu, rs;
    warp_stats(s, ss, mu, rs);
    float* yr = Y + (size_t)w * D_;
#pragma unroll
    for (int j = 0; j < 3; j++) {
        float2 gg = *reinterpret_cast<const float2*>(g + j * 64 + lane * 2);
        float2 bv = *reinterpret_cast<const float2*>(bb + j * 64 + lane * 2);
        *reinterpret_cast<float2*>(yr + j * 64 + lane * 2) =
            make_float2((a[j].x - mu) * rs * gg.x + bv.x, (a[j].y - mu) * rs * gg.y + bv.y);
    }
}

__global__ void dlnw_kernel(const float* __restrict__ X,
                            const float* __restrict__ g1, const float* __restrict__ b1,
                            const float* __restrict__ g2, const float* __restrict__ b2,
                            float* __restrict__ Y, int nrows)
{
    int w = (blockIdx.x * 256 + threadIdx.x) >> 5;
    int lane = threadIdx.x & 31;
    if (w >= nrows) return;
    const float* xr = X + (size_t)w * D_;
    float2 a[3];
    float s = 0.f, ss = 0.f;
#pragma unroll
    for (int j = 0; j < 3; j++) {
        a[j] = *reinterpret_cast<const float2*>(xr + j * 64 + lane * 2);
        s += a[j].x + a[j].y;
        ss += a[j].x * a[j].x + a[j].y * a[j].y;
    }
    float mu, rs;
    warp_stats(s, ss, mu, rs);
    float s2 = 0.f, ss2 = 0.f;
#pragma unroll
    for (int j = 0; j < 3; j++) {
        float2 gg = *reinterpret_cast<const float2*>(g1 + j * 64 + lane * 2);
        float2 bv = *reinterpret_cast<const float2*>(b1 + j * 64 + lane * 2);
        a[j].x = (a[j].x - mu) * rs * gg.x + bv.x;
        a[j].y = (a[j].y - mu) * rs * gg.y + bv.y;
        s2 += a[j].x + a[j].y;
        ss2 += a[j].x * a[j].x + a[j].y * a[j].y;
    }
    warp_stats(s2, ss2, mu, rs);
    float* yr = Y + (size_t)w * D_;
#pragma unroll
    for (int j = 0; j < 3; j++) {
        float2 gg = *reinterpret_cast<const float2*>(g2 + j * 64 + lane * 2);
        float2 bv = *reinterpret_cast<const float2*>(b2 + j * 64 + lane * 2);
        *reinterpret_cast<float2*>(yr + j * 64 + lane * 2) =
            make_float2((a[j].x - mu) * rs * gg.x + bv.x, (a[j].y - mu) * rs * gg.y + bv.y);
    }
}

__global__ void ln_patch_w_kernel(const float* __restrict__ T, const float* __restrict__ g,
                                  const float* __restrict__ bb, const float* __restrict__ pos,
                                  float* __restrict__ XC)
{
    int w = (blockIdx.x * 256 + threadIdx.x) >> 5;   // row in [0, NP_)
    int lane = threadIdx.x & 31;
    if (w >= NP_) return;
    const float* xr = T + (size_t)w * D_;
    float2 a[3];
    float s = 0.f, ss = 0.f;
#pragma unroll
    for (int j = 0; j < 3; j++) {
        a[j] = *reinterpret_cast<const float2*>(xr + j * 64 + lane * 2);
        s += a[j].x + a[j].y;
        ss += a[j].x * a[j].x + a[j].y * a[j].y;
    }
    float mu, rs;
    warp_stats(s, ss, mu, rs);
    int b = w / 196, p = w % 196;
    const float* pr = pos + (size_t)(1 + p) * D_;
    float* yr = XC + ((size_t)b * L_ + 1 + p) * D_;
#pragma unroll
    for (int j = 0; j < 3; j++) {
        float2 gg = *reinterpret_cast<const float2*>(g + j * 64 + lane * 2);
        float2 bv = *reinterpret_cast<const float2*>(bb + j * 64 + lane * 2);
        float2 pp = *reinterpret_cast<const float2*>(pr + j * 64 + lane * 2);
        *reinterpret_cast<float2*>(yr + j * 64 + lane * 2) =
            make_float2((a[j].x - mu) * rs * gg.x + bv.x + pp.x,
                        (a[j].y - mu) * rs * gg.y + bv.y + pp.y);
    }
}

__global__ void cls_kernel(const float* __restrict__ cls, const float* __restrict__ pos,
                           float* __restrict__ XC)
{
    int b = blockIdx.x, tid = threadIdx.x;
    XC[(size_t)b * L_ * D_ + tid] = cls[tid] + pos[tid];
}

// ---------------- mean pool over sequence ----------------
__global__ void pool_kernel(const float* __restrict__ XC, float* __restrict__ P)
{
    int b = blockIdx.x, tid = threadIdx.x;
    float s = 0.f;
    for (int l = 0; l < L_; l++) s += XC[((size_t)b * L_ + l) * D_ + tid];
    P[(size_t)b * D_ + tid] = s * (1.f / 197.f);
}

// ---------------- launcher ----------------
extern "C" void kernel_launch(void* const* d_in, const int* in_sizes, int n_in,
                              void* d_out, int out_size)
{
    (void)in_sizes; (void)n_in; (void)out_size;
    const float* x    = (const float*)d_in[0];
    const float* pw   = (const float*)d_in[1];
    const float* pb   = (const float*)d_in[2];
    const float* peg  = (const float*)d_in[3];
    const float* peb  = (const float*)d_in[4];
    const float* cls  = (const float*)d_in[5];
    const float* pos  = (const float*)d_in[6];
    const float* Wq   = (const float*)d_in[7];
    const float* bq   = (const float*)d_in[8];
    const float* Wk   = (const float*)d_in[9];
    const float* bk   = (const float*)d_in[10];
    const float* Wv   = (const float*)d_in[11];
    const float* bv   = (const float*)d_in[12];
    const float* Wo   = (const float*)d_in[13];
    const float* bo   = (const float*)d_in[14];
    const float* l1g  = (const float*)d_in[15];
    const float* l1b  = (const float*)d_in[16];
    const float* l2g  = (const float*)d_in[17];
    const float* l2b  = (const float*)d_in[18];
    const float* lbg  = (const float*)d_in[19];
    const float* lbb  = (const float*)d_in[20];
    const float* W1   = (const float*)d_in[21];
    const float* b1   = (const float*)d_in[22];
    const float* W2   = (const float*)d_in[23];
    const float* b2   = (const float*)d_in[24];
    const float* om   = (const float*)d_in[25];
    const float* hw   = (const float*)d_in[26];
    const float* hb   = (const float*)d_in[27];
    float* out = (float*)d_out;

    float *xc, *q, *k, *v, *Qp, *Kp, *KVp, *Ksp, *at, *tp, *h1, *pl, *im, *omT;
    cudaGetSymbolAddress((void**)&xc,  g_xc);
    cudaGetSymbolAddress((void**)&q,   g_q);
    cudaGetSymbolAddress((void**)&k,   g_k);
    cudaGetSymbolAddress((void**)&v,   g_v);
    cudaGetSymbolAddress((void**)&Qp,  g_Qp);
    cudaGetSymbolAddress((void**)&Kp,  g_Kp);
    cudaGetSymbolAddress((void**)&KVp, g_KVp);
    cudaGetSymbolAddress((void**)&Ksp, g_Ksp);
    cudaGetSymbolAddress((void**)&at,  g_at);
    cudaGetSymbolAddress((void**)&tp,  g_tp);
    cudaGetSymbolAddress((void**)&h1,  g_h1);
    cudaGetSymbolAddress((void**)&pl,  g_pl);
    cudaGetSymbolAddress((void**)&im,  g_im);
    cudaGetSymbolAddress((void**)&omT, g_omT);

    // ---- one-time: all-layer omega transpose; patch embedding ----
    omt_all_kernel<<<(12 * 8192) / 256, 256>>>(om, omT);
    {
        int tot = NP_ * 768;
        im2col_kernel<<<(tot + 255) / 256, 256>>>(x, im);
        tgemm_kernel<<<dim3(3, NP_ / 128), 256>>>(im, pw, pb, nullptr, q, 768, D_, NP_, 0);
        ln_patch_w_kernel<<<(NP_ * 32 + 255) / 256, 256>>>(q, peg, peb, pos, xc);
        cls_kernel<<<B_, 192>>>(cls, pos, xc);
    }

    const dim3 gD(3, NTP_ / 128);    // Mo=192
    const dim3 gF(12, NTP_ / 128);   // Mo=768
    const int gLN = (NT_ * 32 + 255) / 256;

    for (int i = 0; i < 12; i++) {
        qkv_gemm_kernel<<<dim3(9, NTP_ / 128), 256>>>(
            xc,
            Wq + (size_t)i * D_ * D_, Wk + (size_t)i * D_ * D_, Wv + (size_t)i * D_ * D_,
            bq + i * D_, bk + i * D_, bv + i * D_, q, k, v);
        favor_gemm_kernel<<<dim3(NTP_ / 128, 6), 256>>>(q, k, omT + (size_t)i * 8192, Qp, Kp);
        kv_kernel<<<dim3(B_, H_, 4), 256>>>(Kp, v, KVp, Ksp);
        attn_gemm_kernel<<<dim3(2, B_ * H_), 256>>>(Qp, KVp, Ksp, at);
        // xc_new_pre = xc + attn @ Wo^T + bo
        tgemm_kernel<<<gD, 256>>>(at, Wo + (size_t)i * D_ * D_, bo + i * D_, xc, tp, D_, D_, NTP_, 0);
        lnw_kernel<<<gLN, 256>>>(tp, l1g + i * D_, l1b + i * D_, xc, NT_);
        // MLP
        tgemm_kernel<<<gF, 256>>>(xc, W1 + (size_t)i * FF_ * D_, b1 + i * FF_, nullptr, h1, D_, FF_, NTP_, 1);
        tgemm_kernel<<<gD, 256>>>(h1, W2 + (size_t)i * D_ * FF_, b2 + i * D_, xc, tp, FF_, D_, NTP_, 0);
        dlnw_kernel<<<gLN, 256>>>(tp, l2g + i * D_, l2b + i * D_, lbg + i * D_, lbb + i * D_, xc, NT_);

        if (i == 3 || i == 7 || i == 11) {
            int j = (i == 3) ? 0 : (i == 7) ? 1 : 2;
            pool_kernel<<<B_, 192>>>(xc, pl);
            tgemm_kernel<<<dim3(16, 1), 256>>>(pl, hw + (size_t)j * NCLS_ * D_, hb + j * NCLS_,
                                               nullptr, out + (size_t)j * B_ * NCLS_, D_, NCLS_, B_, 0);
        }
    }
}